// round 11
// baseline (speedup 1.0000x reference)
#include <cuda_runtime.h>
#include <math.h>
#include <stdint.h>

#define Bn 16
#define Qn 300
#define Dn 256
#define Hn 8
#define Pn 4
#define Fn 2048
#define HGn 100
#define WGn 100
#define HWn 10000
#define DHn 32
#define LN_EPS 1e-5f

#define BQ (Bn*Qn)            // 4800
#define MEMROWS (Bn*HWn)      // 160000

typedef unsigned long long ull;

// ---------------- scratch (allocation-free: __device__ globals) ----------------
__device__ float g_qkv[BQ*3*Dn];
__device__ float g_sa[BQ*Dn];
__device__ float g_sap[2*BQ*Dn];      // split-K partial attention accumulators
__device__ float g_su[2*Bn*Hn*Qn];    // split-K partial exp-sums
__device__ float g_x1[BQ*Dn];
__device__ float g_x2[BQ*Dn];
__device__ float g_x2r[BQ*Dn];
__device__ float g_tmp[BQ*Dn];
__device__ float g_ca[BQ*Dn];
__device__ float g_me[Hn*BQ*Dn];      // per-head effective memory vectors [h][bq][d]
__device__ float g_ff[BQ*Fn];
__device__ float g_wcat[Dn*128];
__device__ float g_bcat[128];
__device__ float g_lg[BQ*128];
// tf32-pre-rounded copies
__device__ float g_ipw[Dn*768];
__device__ float g_opw[Dn*Dn];
__device__ float g_vpw[Dn*Dn];
__device__ float g_oqw[Dn*Dn];
__device__ float g_l1w[Dn*Fn];
__device__ float g_l2w[Fn*Dn];
__device__ float g_tgtr[BQ*Dn];

__device__ __forceinline__ uint32_t tf32r(float x) {
    float y;
    asm("cvt.rna.tf32.f32 %0, %1;" : "=f"(y) : "f"(x));
    return __float_as_uint(y);
}
__device__ __forceinline__ float tf32f(float x) { return __uint_as_float(tf32r(x)); }

__device__ __forceinline__ ull fma2(ull a, ull b, ull c) {
    ull d;
    asm("fma.rn.f32x2 %0, %1, %2, %3;" : "=l"(d) : "l"(a), "l"(b), "l"(c));
    return d;
}

union F4U { float4 f; ull u[2]; };
union F2U { float2 f; ull u; };

// ---------------- one-shot tf32 rounding of weights + tgt ----------------
__global__ void round7_kernel(
    const float4* __restrict__ ipw, const float4* __restrict__ opw,
    const float4* __restrict__ vpw, const float4* __restrict__ oqw,
    const float4* __restrict__ l1w, const float4* __restrict__ l2w,
    const float4* __restrict__ tgt,
    float4* d_ipw, float4* d_opw, float4* d_vpw, float4* d_oqw,
    float4* d_l1w, float4* d_l2w, float4* d_tgt)
{
    int bi = blockIdx.x;
    const float4* s; float4* d; int base;
    if      (bi <  192) { s = ipw; d = d_ipw; base = bi; }
    else if (bi <  256) { s = opw; d = d_opw; base = bi - 192; }
    else if (bi <  320) { s = vpw; d = d_vpw; base = bi - 256; }
    else if (bi <  384) { s = oqw; d = d_oqw; base = bi - 320; }
    else if (bi <  896) { s = l1w; d = d_l1w; base = bi - 384; }
    else if (bi < 1408) { s = l2w; d = d_l2w; base = bi - 896; }
    else                { s = tgt; d = d_tgt; base = bi - 1408; }
    int idx = base * 256 + threadIdx.x;
    float4 v = s[idx];
    v.x = tf32f(v.x); v.y = tf32f(v.y); v.z = tf32f(v.z); v.w = tf32f(v.w);
    d[idx] = v;
}

// ---------------- common GEMM constants ----------------
#define TBN 128
#define TBK 16
#define APITCH (TBK + 4)    // 20
#define BPITCH (TBN + 8)    // 136

__device__ __forceinline__ void cp16(void* dst, const void* src) {
    uint32_t d = (uint32_t)__cvta_generic_to_shared(dst);
    asm volatile("cp.async.ca.shared.global [%0], [%1], 16;" :: "r"(d), "l"(src));
}

#define MMA_TF32(c, a, b) \
    asm volatile( \
        "mma.sync.aligned.m16n8k8.row.col.f32.tf32.tf32.f32 " \
        "{%0,%1,%2,%3}, {%4,%5,%6,%7}, {%8,%9}, {%0,%1,%2,%3};" \
        : "+f"((c)[0]), "+f"((c)[1]), "+f"((c)[2]), "+f"((c)[3]) \
        : "r"((a)[0]), "r"((a)[1]), "r"((a)[2]), "r"((a)[3]), \
          "r"((b)[0]), "r"((b)[1]))

// ---------------- generic 64x128 tf32 GEMM (pre-rounded A and B) ----------------
__global__ __launch_bounds__(256) void gemm_tf32_async(
    const float* __restrict__ A, const float* __restrict__ W,
    const float* __restrict__ bias, float* __restrict__ C,
    int M, int N, int K, int relu, int rndout)
{
    extern __shared__ float smem[];
    float (*As)[64][APITCH] = (float(*)[64][APITCH])smem;
    float (*Bs)[TBK][BPITCH] = (float(*)[TBK][BPITCH])(smem + 3 * 64 * APITCH);

    const int tid  = threadIdx.x;
    const int lane = tid & 31;
    const int warp = tid >> 5;
    const int wm = (warp >> 2) * 32;
    const int wn = (warp & 3) * 32;
    const int bm = blockIdx.y * 64;
    const int bn = blockIdx.x * TBN;

    const int lq = lane >> 2;
    const int lr = lane & 3;

    const int a_row = tid >> 2;
    const int a_col = (tid & 3) * 4;
    const int b_row = tid >> 4;
    const int b_col = (tid & 15) * 8;

    const float* Aptr = A + (size_t)(bm + a_row) * K + a_col;
    const float* Wptr = W + (size_t)b_row * N + bn + b_col;

    float c[2][4][4];
#pragma unroll
    for (int i = 0; i < 2; i++)
#pragma unroll
        for (int j = 0; j < 4; j++)
#pragma unroll
            for (int l = 0; l < 4; l++) c[i][j][l] = 0.f;

    const int nk = K / TBK;

#pragma unroll
    for (int s = 0; s < 2; s++) {
        int kt = s * TBK;
        cp16(&As[s][a_row][a_col], Aptr + kt);
        cp16(&Bs[s][b_row][b_col],     Wptr + (size_t)kt * N);
        cp16(&Bs[s][b_row][b_col + 4], Wptr + (size_t)kt * N + 4);
        asm volatile("cp.async.commit_group;" ::: "memory");
    }

    for (int it = 0; it < nk; it++) {
        asm volatile("cp.async.wait_group 1;" ::: "memory");
        __syncthreads();

        int nxt = it + 2;
        if (nxt < nk) {
            int s = nxt % 3;
            int kt = nxt * TBK;
            cp16(&As[s][a_row][a_col], Aptr + kt);
            cp16(&Bs[s][b_row][b_col],     Wptr + (size_t)kt * N);
            cp16(&Bs[s][b_row][b_col + 4], Wptr + (size_t)kt * N + 4);
        }
        asm volatile("cp.async.commit_group;" ::: "memory");

        const int buf = it % 3;
#pragma unroll
        for (int ks = 0; ks < TBK; ks += 8) {
            uint32_t a[2][4], b[4][2];
#pragma unroll
            for (int mt = 0; mt < 2; mt++) {
                int mr = wm + mt * 16 + lq;
                a[mt][0] = __float_as_uint(As[buf][mr    ][ks + lr]);
                a[mt][1] = __float_as_uint(As[buf][mr + 8][ks + lr]);
                a[mt][2] = __float_as_uint(As[buf][mr    ][ks + lr + 4]);
                a[mt][3] = __float_as_uint(As[buf][mr + 8][ks + lr + 4]);
            }
#pragma unroll
            for (int nt = 0; nt < 4; nt++) {
                int nc = wn + nt * 8 + lq;
                b[nt][0] = __float_as_uint(Bs[buf][ks + lr    ][nc]);
                b[nt][1] = __float_as_uint(Bs[buf][ks + lr + 4][nc]);
            }
#pragma unroll
            for (int mt = 0; mt < 2; mt++)
#pragma unroll
                for (int nt = 0; nt < 4; nt++)
                    MMA_TF32(c[mt][nt], a[mt], b[nt]);
        }
    }

#pragma unroll
    for (int mt = 0; mt < 2; mt++) {
#pragma unroll
        for (int nt = 0; nt < 4; nt++) {
            int row = bm + wm + mt * 16 + lq;
            int col = bn + wn + nt * 8 + lr * 2;
            float b0 = bias[col], b1 = bias[col + 1];
            float v0 = c[mt][nt][0] + b0;
            float v1 = c[mt][nt][1] + b1;
            float v2 = c[mt][nt][2] + b0;
            float v3 = c[mt][nt][3] + b1;
            if (relu) {
                v0 = fmaxf(v0, 0.f); v1 = fmaxf(v1, 0.f);
                v2 = fmaxf(v2, 0.f); v3 = fmaxf(v3, 0.f);
            }
            if (rndout) {
                v0 = tf32f(v0); v1 = tf32f(v1); v2 = tf32f(v2); v3 = tf32f(v3);
            }
            *(float2*)&C[(size_t)row * N + col]       = make_float2(v0, v1);
            *(float2*)&C[(size_t)(row + 8) * N + col] = make_float2(v2, v3);
        }
    }
}

// ---------------- per-head projection GEMM: [4800,256]@[256,32] x 8 heads ----------
__global__ __launch_bounds__(128) void gemm_proj(
    const float* __restrict__ A, const float* __restrict__ W,
    const float* __restrict__ bias, float* __restrict__ C)
{
    __shared__ float As[3][64][APITCH];
    __shared__ float Bs[3][TBK][36];

    const int h  = blockIdx.x;       // 0..7
    const int bm = blockIdx.y * 64;
    const int t  = threadIdx.x;      // 0..127
    const int lane = t & 31;
    const int warp = t >> 5;
    const int wm = warp * 16;
    const int lq = lane >> 2;
    const int lr = lane & 3;

    const int a_row = t >> 1;          // 0..63
    const int a_col = (t & 1) * 8;     // 0 or 8
    const int b_row = t >> 3;          // 0..15
    const int b_col = (t & 7) * 4;     // 0..28

    const float* Aptr = A + ((size_t)h * BQ + bm + a_row) * Dn + a_col;
    const float* Wptr = W + (size_t)b_row * Dn + h * 32 + b_col;

    float c[4][4];
#pragma unroll
    for (int j = 0; j < 4; j++)
#pragma unroll
        for (int l = 0; l < 4; l++) c[j][l] = 0.f;

    const int nk = Dn / TBK;  // 16

#pragma unroll
    for (int s = 0; s < 2; s++) {
        int kt = s * TBK;
        cp16(&As[s][a_row][a_col],     Aptr + kt);
        cp16(&As[s][a_row][a_col + 4], Aptr + kt + 4);
        cp16(&Bs[s][b_row][b_col],     Wptr + (size_t)kt * Dn);
        asm volatile("cp.async.commit_group;" ::: "memory");
    }

    for (int it = 0; it < nk; it++) {
        asm volatile("cp.async.wait_group 1;" ::: "memory");
        __syncthreads();

        int nxt = it + 2;
        if (nxt < nk) {
            int s = nxt % 3;
            int kt = nxt * TBK;
            cp16(&As[s][a_row][a_col],     Aptr + kt);
            cp16(&As[s][a_row][a_col + 4], Aptr + kt + 4);
            cp16(&Bs[s][b_row][b_col],     Wptr + (size_t)kt * Dn);
        }
        asm volatile("cp.async.commit_group;" ::: "memory");

        const int buf = it % 3;
#pragma unroll
        for (int ks = 0; ks < TBK; ks += 8) {
            uint32_t a[4], b[4][2];
            int mr = wm + lq;
            a[0] = __float_as_uint(As[buf][mr    ][ks + lr]);
            a[1] = __float_as_uint(As[buf][mr + 8][ks + lr]);
            a[2] = __float_as_uint(As[buf][mr    ][ks + lr + 4]);
            a[3] = __float_as_uint(As[buf][mr + 8][ks + lr + 4]);
#pragma unroll
            for (int nt = 0; nt < 4; nt++) {
                int nc = nt * 8 + lq;
                b[nt][0] = __float_as_uint(Bs[buf][ks + lr    ][nc]);
                b[nt][1] = __float_as_uint(Bs[buf][ks + lr + 4][nc]);
            }
#pragma unroll
            for (int nt = 0; nt < 4; nt++)
                MMA_TF32(c[nt], a, b[nt]);
        }
    }

#pragma unroll
    for (int nt = 0; nt < 4; nt++) {
        int row = bm + wm + lq;
        int col = h * 32 + nt * 8 + lr * 2;
        float b0 = bias[col], b1 = bias[col + 1];
        *(float2*)&C[(size_t)row * Dn + col] =
            make_float2(tf32f(c[nt][0] + b0), tf32f(c[nt][1] + b1));
        *(float2*)&C[(size_t)(row + 8) * Dn + col] =
            make_float2(tf32f(c[nt][2] + b0), tf32f(c[nt][3] + b1));
    }
}

// ---------------- fp32 FFMA tiled SGEMM (accuracy-critical logits) ----------------
#define BM 64
#define BNf 64
#define BKf 16

__global__ __launch_bounds__(256) void gemm_f32_kernel(
    const float* __restrict__ A, const float* __restrict__ W,
    const float* __restrict__ bias, float* __restrict__ C,
    int M, int N, int K)
{
    __shared__ float As[BKf][BM];
    __shared__ float Bs[BKf][BNf];
    int tid = threadIdx.x;
    int tx = tid & 15, ty = tid >> 4;
    int bm = blockIdx.y * BM, bn = blockIdx.x * BNf;

    float acc[4][4];
#pragma unroll
    for (int i = 0; i < 4; i++)
#pragma unroll
        for (int j = 0; j < 4; j++) acc[i][j] = 0.f;

    int a_row = tid >> 2;
    int a_col = (tid & 3) * 4;
    int b_row = tid >> 4;
    int b_col = (tid & 15) * 4;

    const float* Aptr = A + (size_t)(bm + a_row) * K + a_col;
    const float* Wptr = W + (size_t)b_row * N + bn + b_col;

    for (int kt = 0; kt < K; kt += BKf) {
        float4 av = *(const float4*)(Aptr + kt);
        As[a_col + 0][a_row] = av.x;
        As[a_col + 1][a_row] = av.y;
        As[a_col + 2][a_row] = av.z;
        As[a_col + 3][a_row] = av.w;
        float4 bv = *(const float4*)(Wptr + (size_t)kt * N);
        *(float4*)&Bs[b_row][b_col] = bv;
        __syncthreads();
#pragma unroll
        for (int kk = 0; kk < BKf; kk++) {
            float ar[4], br[4];
#pragma unroll
            for (int i = 0; i < 4; i++) ar[i] = As[kk][ty + 16 * i];
#pragma unroll
            for (int j = 0; j < 4; j++) br[j] = Bs[kk][tx + 16 * j];
#pragma unroll
            for (int i = 0; i < 4; i++)
#pragma unroll
                for (int j = 0; j < 4; j++) acc[i][j] += ar[i] * br[j];
        }
        __syncthreads();
    }

#pragma unroll
    for (int i = 0; i < 4; i++) {
        int row = bm + ty + 16 * i;
#pragma unroll
        for (int j = 0; j < 4; j++) {
            int col = bn + tx + 16 * j;
            C[(size_t)row * N + col] = acc[i][j] + bias[col];
        }
    }
}

// ---------------- concat ref/off/attw weights into padded [256,128] ----------------
__global__ void concat_w_kernel(
    const float* __restrict__ ref_w, const float* __restrict__ ref_b,
    const float* __restrict__ off_w, const float* __restrict__ off_b,
    const float* __restrict__ attw_w, const float* __restrict__ attw_b,
    float* __restrict__ Wc, float* __restrict__ bc)
{
    int i = blockIdx.x * 256 + threadIdx.x;
    if (i < Dn * 128) {
        int d = i >> 7, j = i & 127;
        float v = 0.f;
        if (j < 2) v = ref_w[d * 2 + j];
        else if (j < 66) v = off_w[d * 64 + (j - 2)];
        else if (j < 98) v = attw_w[d * 32 + (j - 66)];
        Wc[i] = v;
    }
    if (i < 128) {
        float v = 0.f;
        if (i < 2) v = ref_b[i];
        else if (i < 66) v = off_b[i - 2];
        else if (i < 98) v = attw_b[i - 66];
        bc[i] = v;
    }
}

// ---------------- split-K flash: 2 queries/thread, keys split across blockIdx.y ----
// grid (128, 2): block (bh, ky) processes keys [ky*150, ky*150+150) for all queries.
// Writes UNNORMALIZED partial acc + partial exp-sum; combine kernel finishes.
#define KT2 75   // 150 = 2*75

__global__ __launch_bounds__(160) void flash_kernel(
    const float* __restrict__ qkv, float* __restrict__ sap, float* __restrict__ su)
{
    __shared__ float4 Ks[KT2][8];
    __shared__ float4 Vs[KT2][8];

    const int bh = blockIdx.x;
    const int ky = blockIdx.y;
    const int b = bh >> 3, h = bh & 7;
    const int tid = threadIdx.x;
    const int qi0 = tid;             // 0..159
    const int qi1 = tid + 160;       // 160..319
    const bool act1 = qi1 < Qn;

    ull q0[16], q1[16], a0[16], a1[16];
    const float* qp0 = qkv + (size_t)(b * Qn + qi0) * (3 * Dn) + h * DHn;
    const float* qp1 = qkv + (size_t)(b * Qn + (act1 ? qi1 : 0)) * (3 * Dn) + h * DHn;
#pragma unroll
    for (int i = 0; i < 8; i++) {
        F4U t0; t0.f = *(const float4*)(qp0 + i * 4);
        q0[2 * i] = t0.u[0]; q0[2 * i + 1] = t0.u[1];
        F4U t1; t1.f = *(const float4*)(qp1 + i * 4);
        q1[2 * i] = t1.u[0]; q1[2 * i + 1] = t1.u[1];
    }
#pragma unroll
    for (int i = 0; i < 16; i++) { a0[i] = 0ull; a1[i] = 0ull; }

    float su0 = 0.f, su1 = 0.f;
    const float scale = 0.17677669529663689f;  // 1/sqrt(32)

    const float* kbase = qkv + (size_t)(b * Qn) * (3 * Dn) + Dn + h * DHn;
    const float* vbase = kbase + Dn;
    const int kstart = ky * 150;

#pragma unroll
    for (int tile = 0; tile < 2; tile++) {
        const int t0 = kstart + tile * KT2;
        // cooperative tile load: 600 float4 per array, 160 threads
        for (int i = tid; i < KT2 * 8; i += 160) {
            int j = i >> 3, dc = i & 7;
            size_t off = (size_t)(t0 + j) * (3 * Dn) + dc * 4;
            Ks[j][dc] = *(const float4*)(kbase + off);
            Vs[j][dc] = *(const float4*)(vbase + off);
        }
        __syncthreads();

#pragma unroll 3
        for (int j = 0; j < KT2; j++) {
            F4U w0; w0.f = Ks[j][0]; F4U w1; w1.f = Ks[j][1];
            F4U w2; w2.f = Ks[j][2]; F4U w3; w3.f = Ks[j][3];
            F4U w4; w4.f = Ks[j][4]; F4U w5; w5.f = Ks[j][5];
            F4U w6; w6.f = Ks[j][6]; F4U w7; w7.f = Ks[j][7];
            ull k2a[8] = { w0.u[0], w0.u[1], w1.u[0], w1.u[1],
                           w2.u[0], w2.u[1], w3.u[0], w3.u[1] };
            ull k2b[8] = { w4.u[0], w4.u[1], w5.u[0], w5.u[1],
                           w6.u[0], w6.u[1], w7.u[0], w7.u[1] };

            ull s0a = 0ull, s0b = 0ull, s1a = 0ull, s1b = 0ull;
#pragma unroll
            for (int i = 0; i < 8; i++) {
                s0a = fma2(q0[i], k2a[i], s0a);
                s1a = fma2(q1[i], k2a[i], s1a);
                s0b = fma2(q0[8 + i], k2b[i], s0b);
                s1b = fma2(q1[8 + i], k2b[i], s1b);
            }
            F2U u0a; u0a.u = s0a; F2U u0b; u0b.u = s0b;
            F2U u1a; u1a.u = s1a; F2U u1b; u1b.u = s1b;
            float s0 = (u0a.f.x + u0a.f.y + u0b.f.x + u0b.f.y) * scale;
            float s1 = (u1a.f.x + u1a.f.y + u1b.f.x + u1b.f.y) * scale;
            float p0 = __expf(s0);
            float p1 = __expf(s1);
            su0 += p0;
            su1 += p1;
            F2U pp0; pp0.f = make_float2(p0, p0);
            F2U pp1; pp1.f = make_float2(p1, p1);
            ull p02 = pp0.u, p12 = pp1.u;

            F4U v0; v0.f = Vs[j][0]; F4U v1; v1.f = Vs[j][1];
            F4U v2; v2.f = Vs[j][2]; F4U v3; v3.f = Vs[j][3];
            F4U v4; v4.f = Vs[j][4]; F4U v5; v5.f = Vs[j][5];
            F4U v6; v6.f = Vs[j][6]; F4U v7; v7.f = Vs[j][7];
            ull vv[16] = { v0.u[0], v0.u[1], v1.u[0], v1.u[1],
                           v2.u[0], v2.u[1], v3.u[0], v3.u[1],
                           v4.u[0], v4.u[1], v5.u[0], v5.u[1],
                           v6.u[0], v6.u[1], v7.u[0], v7.u[1] };
#pragma unroll
            for (int i = 0; i < 16; i++) {
                a0[i] = fma2(p02, vv[i], a0[i]);
                a1[i] = fma2(p12, vv[i], a1[i]);
            }
        }
        __syncthreads();
    }

    // write unnormalized partials
    const size_t half = (size_t)ky * BQ * Dn;
    {
        float* op0 = sap + half + (size_t)(b * Qn + qi0) * Dn + h * DHn;
#pragma unroll
        for (int i = 0; i < 8; i++) {
            F2U lo; lo.u = a0[2 * i];
            F2U hi; hi.u = a0[2 * i + 1];
            *(float4*)(op0 + i * 4) = make_float4(lo.f.x, lo.f.y, hi.f.x, hi.f.y);
        }
        su[(size_t)(ky * 128 + bh) * Qn + qi0] = su0;
    }
    if (act1) {
        float* op1 = sap + half + (size_t)(b * Qn + qi1) * Dn + h * DHn;
#pragma unroll
        for (int i = 0; i < 8; i++) {
            F2U lo; lo.u = a1[2 * i];
            F2U hi; hi.u = a1[2 * i + 1];
            *(float4*)(op1 + i * 4) = make_float4(lo.f.x, lo.f.y, hi.f.x, hi.f.y);
        }
        su[(size_t)(ky * 128 + bh) * Qn + qi1] = su1;
    }
}

// ---------------- flash combine: sa = (a0+a1)/(su0+su1), tf32-rounded -------------
__global__ void flash_combine_kernel(
    const float* __restrict__ sap, const float* __restrict__ su,
    float* __restrict__ sa)
{
    int bq = blockIdx.x;
    int t = threadIdx.x;            // 0..255
    int b = bq / Qn, q = bq - b * Qn;
    int h = t >> 5;
    int bh = b * Hn + h;
    float s = su[(size_t)bh * Qn + q] + su[(size_t)(128 + bh) * Qn + q];
    size_t idx = (size_t)bq * Dn + t;
    float v = (sap[idx] + sap[(size_t)BQ * Dn + idx]) / s;
    sa[idx] = tf32f(v);
}

// ---------------- fused residual-add + LayerNorm ----------------
__global__ void add_ln_kernel(const float* __restrict__ a, const float* __restrict__ r,
                              const float* __restrict__ g, const float* __restrict__ be,
                              float* __restrict__ out, float* __restrict__ out_r)
{
    int row = blockIdx.x, t = threadIdx.x;
    size_t idx = (size_t)row * Dn + t;
    float v = a[idx] + r[idx];
    __shared__ float red[8];
    float s = v;
#pragma unroll
    for (int o = 16; o; o >>= 1) s += __shfl_xor_sync(~0u, s, o);
    if ((t & 31) == 0) red[t >> 5] = s;
    __syncthreads();
    float mean = 0.f;
#pragma unroll
    for (int i = 0; i < 8; i++) mean += red[i];
    mean *= (1.f / Dn);
    float d = v - mean;
    float s2 = d * d;
#pragma unroll
    for (int o = 16; o; o >>= 1) s2 += __shfl_xor_sync(~0u, s2, o);
    __syncthreads();
    if ((t & 31) == 0) red[t >> 5] = s2;
    __syncthreads();
    float var = 0.f;
#pragma unroll
    for (int i = 0; i < 8; i++) var += red[i];
    var *= (1.f / Dn);
    float o2 = d * rsqrtf(var + LN_EPS) * g[t] + be[t];
    out[idx] = o2;
    if (out_r) out_r[idx] = tf32f(o2);
}

// ---------------- sampler2: weights + bilinear gather of RAW memory -> m_eff ------
__global__ __launch_bounds__(256) void sampler2_kernel(
    const float* __restrict__ lgbuf, const float* __restrict__ memory,
    float* __restrict__ me)
{
    __shared__ float lg[128];
    __shared__ float sref[2];
    __shared__ float swts[Hn * Pn];
    __shared__ int   srow[128];
    __shared__ float swt[128];

    int bq = blockIdx.x;
    int b = bq / Qn;
    int t = threadIdx.x;

    if (t < 128) lg[t] = lgbuf[(size_t)bq * 128 + t];
    __syncthreads();

    if (t < 2) sref[t] = 1.f / (1.f + expf(-lg[t]));
    else if (t >= 32 && t < 40) {
        int h = t - 32;
        const float* al = &lg[66 + h * 4];
        float m = fmaxf(fmaxf(al[0], al[1]), fmaxf(al[2], al[3]));
        float e0 = expf(al[0]-m), e1 = expf(al[1]-m), e2 = expf(al[2]-m), e3 = expf(al[3]-m);
        float inv = 1.f / (e0 + e1 + e2 + e3);
        swts[h*4+0] = e0*inv; swts[h*4+1] = e1*inv; swts[h*4+2] = e2*inv; swts[h*4+3] = e3*inv;
    }
    __syncthreads();

    if (t < 32) {
        int h = t >> 2, p = t & 3;
        float lx = fminf(fmaxf(sref[0] + lg[2 + h * 8 + p * 2 + 0], 0.f), 1.f);
        float ly = fminf(fmaxf(sref[1] + lg[2 + h * 8 + p * 2 + 1], 0.f), 1.f);
        float sx = lx * (float)(WGn - 1);
        float sy = ly * (float)(HGn - 1);
        float x0f = floorf(sx), y0f = floorf(sy);
        int x0 = min(max((int)x0f, 0), WGn - 1);
        int y0 = min(max((int)y0f, 0), HGn - 1);
        int x1i = min(x0 + 1, WGn - 1);
        int y1i = min(y0 + 1, HGn - 1);
        float wx1 = sx - x0f, wx0 = 1.f - wx1;
        float wy1 = sy - y0f, wy0 = 1.f - wy1;
        float wp = swts[t];
        int rowb = b * HWn;
        int base = t * 4;
        srow[base + 0] = rowb + y0  * WGn + x0;  swt[base + 0] = wp * wx0 * wy0;
        srow[base + 1] = rowb + y1i * WGn + x0;  swt[base + 1] = wp * wx0 * wy1;
        srow[base + 2] = rowb + y0  * WGn + x1i; swt[base + 2] = wp * wx1 * wy0;
        srow[base + 3] = rowb + y1i * WGn + x1i; swt[base + 3] = wp * wx1 * wy1;
    }
    __syncthreads();

#pragma unroll
    for (int h = 0; h < Hn; h++) {
        float acc = 0.f;
#pragma unroll
        for (int i = 0; i < 16; i++)
            acc += swt[h * 16 + i] * memory[(size_t)srow[h * 16 + i] * Dn + t];
        me[((size_t)h * BQ + bq) * Dn + t] = tf32f(acc);
    }
}

// ---------------- launch ----------------
extern "C" void kernel_launch(void* const* d_in, const int* in_sizes, int n_in,
                              void* d_out, int out_size)
{
    const float* tgt        = (const float*)d_in[0];
    const float* memory     = (const float*)d_in[1];
    const float* in_proj_w  = (const float*)d_in[2];
    const float* in_proj_b  = (const float*)d_in[3];
    const float* out_proj_w = (const float*)d_in[4];
    const float* out_proj_b = (const float*)d_in[5];
    const float* norm1_g    = (const float*)d_in[6];
    const float* norm1_b    = (const float*)d_in[7];
    const float* ref_w      = (const float*)d_in[8];
    const float* ref_b      = (const float*)d_in[9];
    const float* off_w      = (const float*)d_in[10];
    const float* off_b      = (const float*)d_in[11];
    const float* attw_w     = (const float*)d_in[12];
    const float* attw_b     = (const float*)d_in[13];
    const float* vproj_w    = (const float*)d_in[14];
    const float* vproj_b    = (const float*)d_in[15];
    const float* oproj_w    = (const float*)d_in[16];
    const float* oproj_b    = (const float*)d_in[17];
    const float* norm2_g    = (const float*)d_in[18];
    const float* norm2_b    = (const float*)d_in[19];
    const float* lin1_w     = (const float*)d_in[20];
    const float* lin1_b     = (const float*)d_in[21];
    const float* lin2_w     = (const float*)d_in[22];
    const float* lin2_b     = (const float*)d_in[23];
    const float* norm3_g    = (const float*)d_in[24];
    const float* norm3_b    = (const float*)d_in[25];
    float* out = (float*)d_out;

    float *qkv, *sa, *sap, *suf, *x1, *x2, *x2r, *tmp, *ca, *me, *ff, *wcat, *bcat, *lgb;
    float *ipw, *opw, *vpw, *oqw, *l1w, *l2w, *tgtr;
    cudaGetSymbolAddress((void**)&qkv,  g_qkv);
    cudaGetSymbolAddress((void**)&sa,   g_sa);
    cudaGetSymbolAddress((void**)&sap,  g_sap);
    cudaGetSymbolAddress((void**)&suf,  g_su);
    cudaGetSymbolAddress((void**)&x1,   g_x1);
    cudaGetSymbolAddress((void**)&x2,   g_x2);
    cudaGetSymbolAddress((void**)&x2r,  g_x2r);
    cudaGetSymbolAddress((void**)&tmp,  g_tmp);
    cudaGetSymbolAddress((void**)&ca,   g_ca);
    cudaGetSymbolAddress((void**)&me,   g_me);
    cudaGetSymbolAddress((void**)&ff,   g_ff);
    cudaGetSymbolAddress((void**)&wcat, g_wcat);
    cudaGetSymbolAddress((void**)&bcat, g_bcat);
    cudaGetSymbolAddress((void**)&lgb,  g_lg);
    cudaGetSymbolAddress((void**)&ipw,  g_ipw);
    cudaGetSymbolAddress((void**)&opw,  g_opw);
    cudaGetSymbolAddress((void**)&vpw,  g_vpw);
    cudaGetSymbolAddress((void**)&oqw,  g_oqw);
    cudaGetSymbolAddress((void**)&l1w,  g_l1w);
    cudaGetSymbolAddress((void**)&l2w,  g_l2w);
    cudaGetSymbolAddress((void**)&tgtr, g_tgtr);

    const int smem1 = (3 * 64 * APITCH + 3 * TBK * BPITCH) * 4;  // 41472
    cudaFuncSetAttribute((const void*)gemm_tf32_async, cudaFuncAttributeMaxDynamicSharedMemorySize, smem1);

    // 0. pre-round weights + tgt; concat logits weights (fp32)
    round7_kernel<<<2608, 256>>>(
        (const float4*)in_proj_w, (const float4*)out_proj_w, (const float4*)vproj_w,
        (const float4*)oproj_w, (const float4*)lin1_w, (const float4*)lin2_w,
        (const float4*)tgt,
        (float4*)ipw, (float4*)opw, (float4*)vpw, (float4*)oqw,
        (float4*)l1w, (float4*)l2w, (float4*)tgtr);
    concat_w_kernel<<<128, 256>>>(ref_w, ref_b, off_w, off_b, attw_w, attw_b, wcat, bcat);
    // 1. qkv projection [4800,256]@[256,768]
    gemm_tf32_async<<<dim3(768 / TBN, BQ / 64), 256, smem1>>>(tgtr, ipw, in_proj_b, qkv, BQ, 768, Dn, 0, 0);
    // 2. split-K flash + combine
    flash_kernel<<<dim3(Bn * Hn, 2), 160>>>(qkv, sap, suf);
    flash_combine_kernel<<<BQ, 256>>>(sap, suf, sa);
    // 3. out_proj
    gemm_tf32_async<<<dim3(Dn / TBN, BQ / 64), 256, smem1>>>(sa, opw, out_proj_b, tmp, BQ, Dn, Dn, 0, 0);
    // 4. x1 = LN(tgt + sa_out)
    add_ln_kernel<<<BQ, Dn>>>(tgt, tmp, norm1_g, norm1_b, x1, nullptr);
    // 5. logits — fp32 (accuracy-critical)
    gemm_f32_kernel<<<dim3(128 / BNf, BQ / BM), 256>>>(x1, wcat, bcat, lgb, BQ, 128, Dn);
    // 6. sampler2: gather raw memory into per-head effective vectors
    sampler2_kernel<<<BQ, 256>>>(lgb, memory, me);
    // 7. per-head projection: ca = m_eff @ vproj_w (+bias)
    gemm_proj<<<dim3(Hn, BQ / 64), 128>>>(me, vpw, vproj_b, ca);
    // 8. oproj
    gemm_tf32_async<<<dim3(Dn / TBN, BQ / 64), 256, smem1>>>(ca, oqw, oproj_b, tmp, BQ, Dn, Dn, 0, 0);
    // 9. x2 = LN(x1 + ca_out); x2r = tf32(x2)
    add_ln_kernel<<<BQ, Dn>>>(x1, tmp, norm2_g, norm2_b, x2, x2r);
    // 10. FFN lin1 + ReLU (tf32-rounded out)
    gemm_tf32_async<<<dim3(Fn / TBN, BQ / 64), 256, smem1>>>(x2r, l1w, lin1_b, ff, BQ, Fn, Dn, 1, 1);
    // 11. FFN lin2
    gemm_tf32_async<<<dim3(Dn / TBN, BQ / 64), 256, smem1>>>(ff, l2w, lin2_b, tmp, BQ, Dn, Fn, 0, 0);
    // 12. out = LN(x2 + ffn)
    add_ln_kernel<<<BQ, Dn>>>(x2, tmp, norm3_g, norm3_b, out, nullptr);
}

// round 12
// speedup vs baseline: 1.1778x; 1.1778x over previous
#include <cuda_runtime.h>
#include <cuda_fp16.h>
#include <math.h>
#include <stdint.h>

#define Bn 16
#define Qn 300
#define Dn 256
#define Hn 8
#define Pn 4
#define Fn 2048
#define HGn 100
#define WGn 100
#define HWn 10000
#define DHn 32
#define LN_EPS 1e-5f

#define BQ (Bn*Qn)            // 4800
#define MEMROWS (Bn*HWn)      // 160000

typedef unsigned long long ull;

// ---------------- scratch (allocation-free: __device__ globals) ----------------
__device__ float g_qkv[BQ*3*Dn];
__device__ float g_sa[BQ*Dn];
__device__ float g_x1[BQ*Dn];
__device__ float g_x2[BQ*Dn];
__device__ __half g_x2h[BQ*Dn];
__device__ float g_tmp[BQ*Dn];
__device__ float g_ca[BQ*Dn];
__device__ float g_me[Hn*BQ*Dn];
__device__ __half g_ffh[BQ*Fn];
__device__ float g_wcat[Dn*128];
__device__ float g_bcat[128];
__device__ float g_lg[BQ*128];
// tf32-pre-rounded copies
__device__ float g_ipw[Dn*768];
__device__ float g_opw[Dn*Dn];
__device__ float g_vpw[Dn*Dn];
__device__ float g_oqw[Dn*Dn];
__device__ float g_tgtr[BQ*Dn];
// fp16 k-pair-packed FFN weights
__device__ uint32_t g_p1w[(Dn/2)*Fn];   // [128][2048]
__device__ uint32_t g_p2w[(Fn/2)*Dn];   // [1024][256]

__device__ __forceinline__ uint32_t tf32r(float x) {
    float y;
    asm("cvt.rna.tf32.f32 %0, %1;" : "=f"(y) : "f"(x));
    return __float_as_uint(y);
}
__device__ __forceinline__ float tf32f(float x) { return __uint_as_float(tf32r(x)); }

__device__ __forceinline__ ull fma2(ull a, ull b, ull c) {
    ull d;
    asm("fma.rn.f32x2 %0, %1, %2, %3;" : "=l"(d) : "l"(a), "l"(b), "l"(c));
    return d;
}

union F4U { float4 f; ull u[2]; };
union F2U { float2 f; ull u; };

// ---------------- one-shot tf32 rounding of weights + tgt ----------------
// segments (float4 blocks of 256): ipw 192 | opw 64 | vpw 64 | oqw 64 | tgt 1200
__global__ void round5_kernel(
    const float4* __restrict__ ipw, const float4* __restrict__ opw,
    const float4* __restrict__ vpw, const float4* __restrict__ oqw,
    const float4* __restrict__ tgt,
    float4* d_ipw, float4* d_opw, float4* d_vpw, float4* d_oqw, float4* d_tgt)
{
    int bi = blockIdx.x;
    const float4* s; float4* d; int base;
    if      (bi <  192) { s = ipw; d = d_ipw; base = bi; }
    else if (bi <  256) { s = opw; d = d_opw; base = bi - 192; }
    else if (bi <  320) { s = vpw; d = d_vpw; base = bi - 256; }
    else if (bi <  384) { s = oqw; d = d_oqw; base = bi - 320; }
    else                { s = tgt; d = d_tgt; base = bi - 384; }
    int idx = base * 256 + threadIdx.x;
    float4 v = s[idx];
    v.x = tf32f(v.x); v.y = tf32f(v.y); v.z = tf32f(v.z); v.w = tf32f(v.w);
    d[idx] = v;
}

// ---------------- pack FFN weights into fp16 k-pair half2 ----------------
__global__ void packh_kernel(
    const float* __restrict__ l1w, const float* __restrict__ l2w,
    uint32_t* __restrict__ p1, uint32_t* __restrict__ p2)
{
    int i = blockIdx.x * 256 + threadIdx.x;   // 0..262143
    {
        int k2 = i >> 11, n = i & 2047;       // l1w [256][2048]
        __half2 h = __floats2half2_rn(l1w[(2*k2) * Fn + n], l1w[(2*k2+1) * Fn + n]);
        p1[i] = *(uint32_t*)&h;
    }
    {
        int k2 = i >> 8, n = i & 255;          // l2w [2048][256]
        __half2 h = __floats2half2_rn(l2w[(2*k2) * Dn + n], l2w[(2*k2+1) * Dn + n]);
        p2[i] = *(uint32_t*)&h;
    }
}

// ---------------- common GEMM constants ----------------
#define TBN 128
#define TBK 16
#define APITCH (TBK + 4)    // 20
#define BPITCH (TBN + 8)    // 136

__device__ __forceinline__ void cp16(void* dst, const void* src) {
    uint32_t d = (uint32_t)__cvta_generic_to_shared(dst);
    asm volatile("cp.async.ca.shared.global [%0], [%1], 16;" :: "r"(d), "l"(src));
}

#define MMA_TF32(c, a, b) \
    asm volatile( \
        "mma.sync.aligned.m16n8k8.row.col.f32.tf32.tf32.f32 " \
        "{%0,%1,%2,%3}, {%4,%5,%6,%7}, {%8,%9}, {%0,%1,%2,%3};" \
        : "+f"((c)[0]), "+f"((c)[1]), "+f"((c)[2]), "+f"((c)[3]) \
        : "r"((a)[0]), "r"((a)[1]), "r"((a)[2]), "r"((a)[3]), \
          "r"((b)[0]), "r"((b)[1]))

#define MMA_F16(c, a, b) \
    asm volatile( \
        "mma.sync.aligned.m16n8k16.row.col.f32.f16.f16.f32 " \
        "{%0,%1,%2,%3}, {%4,%5,%6,%7}, {%8,%9}, {%0,%1,%2,%3};" \
        : "+f"((c)[0]), "+f"((c)[1]), "+f"((c)[2]), "+f"((c)[3]) \
        : "r"((a)[0]), "r"((a)[1]), "r"((a)[2]), "r"((a)[3]), \
          "r"((b)[0]), "r"((b)[1]))

// ---------------- generic 64x128 tf32 GEMM (pre-rounded A and B) ----------------
__global__ __launch_bounds__(256) void gemm_tf32_async(
    const float* __restrict__ A, const float* __restrict__ W,
    const float* __restrict__ bias, float* __restrict__ C,
    int M, int N, int K, int relu, int rndout)
{
    extern __shared__ float smem[];
    float (*As)[64][APITCH] = (float(*)[64][APITCH])smem;
    float (*Bs)[TBK][BPITCH] = (float(*)[TBK][BPITCH])(smem + 3 * 64 * APITCH);

    const int tid  = threadIdx.x;
    const int lane = tid & 31;
    const int warp = tid >> 5;
    const int wm = (warp >> 2) * 32;
    const int wn = (warp & 3) * 32;
    const int bm = blockIdx.y * 64;
    const int bn = blockIdx.x * TBN;

    const int lq = lane >> 2;
    const int lr = lane & 3;

    const int a_row = tid >> 2;
    const int a_col = (tid & 3) * 4;
    const int b_row = tid >> 4;
    const int b_col = (tid & 15) * 8;

    const float* Aptr = A + (size_t)(bm + a_row) * K + a_col;
    const float* Wptr = W + (size_t)b_row * N + bn + b_col;

    float c[2][4][4];
#pragma unroll
    for (int i = 0; i < 2; i++)
#pragma unroll
        for (int j = 0; j < 4; j++)
#pragma unroll
            for (int l = 0; l < 4; l++) c[i][j][l] = 0.f;

    const int nk = K / TBK;

#pragma unroll
    for (int s = 0; s < 2; s++) {
        int kt = s * TBK;
        cp16(&As[s][a_row][a_col], Aptr + kt);
        cp16(&Bs[s][b_row][b_col],     Wptr + (size_t)kt * N);
        cp16(&Bs[s][b_row][b_col + 4], Wptr + (size_t)kt * N + 4);
        asm volatile("cp.async.commit_group;" ::: "memory");
    }

    for (int it = 0; it < nk; it++) {
        asm volatile("cp.async.wait_group 1;" ::: "memory");
        __syncthreads();

        int nxt = it + 2;
        if (nxt < nk) {
            int s = nxt % 3;
            int kt = nxt * TBK;
            cp16(&As[s][a_row][a_col], Aptr + kt);
            cp16(&Bs[s][b_row][b_col],     Wptr + (size_t)kt * N);
            cp16(&Bs[s][b_row][b_col + 4], Wptr + (size_t)kt * N + 4);
        }
        asm volatile("cp.async.commit_group;" ::: "memory");

        const int buf = it % 3;
#pragma unroll
        for (int ks = 0; ks < TBK; ks += 8) {
            uint32_t a[2][4], b[4][2];
#pragma unroll
            for (int mt = 0; mt < 2; mt++) {
                int mr = wm + mt * 16 + lq;
                a[mt][0] = __float_as_uint(As[buf][mr    ][ks + lr]);
                a[mt][1] = __float_as_uint(As[buf][mr + 8][ks + lr]);
                a[mt][2] = __float_as_uint(As[buf][mr    ][ks + lr + 4]);
                a[mt][3] = __float_as_uint(As[buf][mr + 8][ks + lr + 4]);
            }
#pragma unroll
            for (int nt = 0; nt < 4; nt++) {
                int nc = wn + nt * 8 + lq;
                b[nt][0] = __float_as_uint(Bs[buf][ks + lr    ][nc]);
                b[nt][1] = __float_as_uint(Bs[buf][ks + lr + 4][nc]);
            }
#pragma unroll
            for (int mt = 0; mt < 2; mt++)
#pragma unroll
                for (int nt = 0; nt < 4; nt++)
                    MMA_TF32(c[mt][nt], a[mt], b[nt]);
        }
    }

#pragma unroll
    for (int mt = 0; mt < 2; mt++) {
#pragma unroll
        for (int nt = 0; nt < 4; nt++) {
            int row = bm + wm + mt * 16 + lq;
            int col = bn + wn + nt * 8 + lr * 2;
            float b0 = bias[col], b1 = bias[col + 1];
            float v0 = c[mt][nt][0] + b0;
            float v1 = c[mt][nt][1] + b1;
            float v2 = c[mt][nt][2] + b0;
            float v3 = c[mt][nt][3] + b1;
            if (relu) {
                v0 = fmaxf(v0, 0.f); v1 = fmaxf(v1, 0.f);
                v2 = fmaxf(v2, 0.f); v3 = fmaxf(v3, 0.f);
            }
            if (rndout) {
                v0 = tf32f(v0); v1 = tf32f(v1); v2 = tf32f(v2); v3 = tf32f(v3);
            }
            *(float2*)&C[(size_t)row * N + col]       = make_float2(v0, v1);
            *(float2*)&C[(size_t)(row + 8) * N + col] = make_float2(v2, v3);
        }
    }
}

// ---------------- fp16 64x128 GEMM (m16n8k16), 3-stage cp.async --------------------
// A: half row-major [M][K]; Wpk: k-pair-packed half2 [K/2][N] (uint32); TBK=32.
#define HBK 32
#define HAP 20     // A pitch in u32 (16 data + 4 pad)

__global__ __launch_bounds__(256) void gemm_fp16_async(
    const __half* __restrict__ A, const uint32_t* __restrict__ Wpk,
    const float* __restrict__ bias, void* __restrict__ Cout,
    int M, int N, int K, int relu, int outhalf)
{
    extern __shared__ uint32_t smemu[];
    uint32_t (*As)[64][HAP]    = (uint32_t(*)[64][HAP])smemu;
    uint32_t (*Bs)[16][BPITCH] = (uint32_t(*)[16][BPITCH])(smemu + 3 * 64 * HAP);

    const int tid  = threadIdx.x;
    const int lane = tid & 31;
    const int warp = tid >> 5;
    const int wm = (warp >> 2) * 32;
    const int wn = (warp & 3) * 32;
    const int bm = blockIdx.y * 64;
    const int bn = blockIdx.x * TBN;

    const int lq = lane >> 2;
    const int lr = lane & 3;

    const int a_row = tid >> 2;          // 0..63
    const int a_u32 = (tid & 3) * 4;     // 0,4,8,12 (u32 units; *2 = half units)
    const int b_row = tid >> 4;          // 0..15 (k2 within tile)
    const int b_u32 = (tid & 15) * 8;    // 0..120

    const __half* Aptr = A + (size_t)(bm + a_row) * K + a_u32 * 2;
    const uint32_t* Wptr = Wpk + (size_t)b_row * N + bn + b_u32;

    float c[2][4][4];
#pragma unroll
    for (int i = 0; i < 2; i++)
#pragma unroll
        for (int j = 0; j < 4; j++)
#pragma unroll
            for (int l = 0; l < 4; l++) c[i][j][l] = 0.f;

    const int nk = K / HBK;

#pragma unroll
    for (int s = 0; s < 2; s++) {
        int kt = s * HBK;
        cp16(&As[s][a_row][a_u32], Aptr + kt);
        cp16(&Bs[s][b_row][b_u32],     Wptr + (size_t)(kt / 2) * N);
        cp16(&Bs[s][b_row][b_u32 + 4], Wptr + (size_t)(kt / 2) * N + 4);
        asm volatile("cp.async.commit_group;" ::: "memory");
    }

    for (int it = 0; it < nk; it++) {
        asm volatile("cp.async.wait_group 1;" ::: "memory");
        __syncthreads();

        int nxt = it + 2;
        if (nxt < nk) {
            int s = nxt % 3;
            int kt = nxt * HBK;
            cp16(&As[s][a_row][a_u32], Aptr + kt);
            cp16(&Bs[s][b_row][b_u32],     Wptr + (size_t)(kt / 2) * N);
            cp16(&Bs[s][b_row][b_u32 + 4], Wptr + (size_t)(kt / 2) * N + 4);
        }
        asm volatile("cp.async.commit_group;" ::: "memory");

        const int buf = it % 3;
#pragma unroll
        for (int ks2 = 0; ks2 < 16; ks2 += 8) {   // two k16 steps per 32-K tile
            uint32_t a[2][4], b[4][2];
#pragma unroll
            for (int mt = 0; mt < 2; mt++) {
                int mr = wm + mt * 16 + lq;
                a[mt][0] = As[buf][mr    ][ks2 + lr];
                a[mt][1] = As[buf][mr + 8][ks2 + lr];
                a[mt][2] = As[buf][mr    ][ks2 + lr + 4];
                a[mt][3] = As[buf][mr + 8][ks2 + lr + 4];
            }
#pragma unroll
            for (int nt = 0; nt < 4; nt++) {
                int nc = wn + nt * 8 + lq;
                b[nt][0] = Bs[buf][ks2 + lr    ][nc];
                b[nt][1] = Bs[buf][ks2 + lr + 4][nc];
            }
#pragma unroll
            for (int mt = 0; mt < 2; mt++)
#pragma unroll
                for (int nt = 0; nt < 4; nt++)
                    MMA_F16(c[mt][nt], a[mt], b[nt]);
        }
    }

#pragma unroll
    for (int mt = 0; mt < 2; mt++) {
#pragma unroll
        for (int nt = 0; nt < 4; nt++) {
            int row = bm + wm + mt * 16 + lq;
            int col = bn + wn + nt * 8 + lr * 2;
            float b0 = bias[col], b1 = bias[col + 1];
            float v0 = c[mt][nt][0] + b0;
            float v1 = c[mt][nt][1] + b1;
            float v2 = c[mt][nt][2] + b0;
            float v3 = c[mt][nt][3] + b1;
            if (relu) {
                v0 = fmaxf(v0, 0.f); v1 = fmaxf(v1, 0.f);
                v2 = fmaxf(v2, 0.f); v3 = fmaxf(v3, 0.f);
            }
            if (outhalf) {
                __half* C = (__half*)Cout;
                __half2 h0 = __floats2half2_rn(v0, v1);
                __half2 h1 = __floats2half2_rn(v2, v3);
                *(__half2*)&C[(size_t)row * N + col]       = h0;
                *(__half2*)&C[(size_t)(row + 8) * N + col] = h1;
            } else {
                float* C = (float*)Cout;
                *(float2*)&C[(size_t)row * N + col]       = make_float2(v0, v1);
                *(float2*)&C[(size_t)(row + 8) * N + col] = make_float2(v2, v3);
            }
        }
    }
}

// ---------------- per-head projection GEMM: [4800,256]@[256,32] x 8 heads ----------
__global__ __launch_bounds__(128) void gemm_proj(
    const float* __restrict__ A, const float* __restrict__ W,
    const float* __restrict__ bias, float* __restrict__ C)
{
    __shared__ float As[3][64][APITCH];
    __shared__ float Bs[3][TBK][36];

    const int h  = blockIdx.x;
    const int bm = blockIdx.y * 64;
    const int t  = threadIdx.x;
    const int lane = t & 31;
    const int warp = t >> 5;
    const int wm = warp * 16;
    const int lq = lane >> 2;
    const int lr = lane & 3;

    const int a_row = t >> 1;
    const int a_col = (t & 1) * 8;
    const int b_row = t >> 3;
    const int b_col = (t & 7) * 4;

    const float* Aptr = A + ((size_t)h * BQ + bm + a_row) * Dn + a_col;
    const float* Wptr = W + (size_t)b_row * Dn + h * 32 + b_col;

    float c[4][4];
#pragma unroll
    for (int j = 0; j < 4; j++)
#pragma unroll
        for (int l = 0; l < 4; l++) c[j][l] = 0.f;

    const int nk = Dn / TBK;

#pragma unroll
    for (int s = 0; s < 2; s++) {
        int kt = s * TBK;
        cp16(&As[s][a_row][a_col],     Aptr + kt);
        cp16(&As[s][a_row][a_col + 4], Aptr + kt + 4);
        cp16(&Bs[s][b_row][b_col],     Wptr + (size_t)kt * Dn);
        asm volatile("cp.async.commit_group;" ::: "memory");
    }

    for (int it = 0; it < nk; it++) {
        asm volatile("cp.async.wait_group 1;" ::: "memory");
        __syncthreads();

        int nxt = it + 2;
        if (nxt < nk) {
            int s = nxt % 3;
            int kt = nxt * TBK;
            cp16(&As[s][a_row][a_col],     Aptr + kt);
            cp16(&As[s][a_row][a_col + 4], Aptr + kt + 4);
            cp16(&Bs[s][b_row][b_col],     Wptr + (size_t)kt * Dn);
        }
        asm volatile("cp.async.commit_group;" ::: "memory");

        const int buf = it % 3;
#pragma unroll
        for (int ks = 0; ks < TBK; ks += 8) {
            uint32_t a[4], b[4][2];
            int mr = wm + lq;
            a[0] = __float_as_uint(As[buf][mr    ][ks + lr]);
            a[1] = __float_as_uint(As[buf][mr + 8][ks + lr]);
            a[2] = __float_as_uint(As[buf][mr    ][ks + lr + 4]);
            a[3] = __float_as_uint(As[buf][mr + 8][ks + lr + 4]);
#pragma unroll
            for (int nt = 0; nt < 4; nt++) {
                int nc = nt * 8 + lq;
                b[nt][0] = __float_as_uint(Bs[buf][ks + lr    ][nc]);
                b[nt][1] = __float_as_uint(Bs[buf][ks + lr + 4][nc]);
            }
#pragma unroll
            for (int nt = 0; nt < 4; nt++)
                MMA_TF32(c[nt], a, b[nt]);
        }
    }

#pragma unroll
    for (int nt = 0; nt < 4; nt++) {
        int row = bm + wm + lq;
        int col = h * 32 + nt * 8 + lr * 2;
        float b0 = bias[col], b1 = bias[col + 1];
        *(float2*)&C[(size_t)row * Dn + col] =
            make_float2(tf32f(c[nt][0] + b0), tf32f(c[nt][1] + b1));
        *(float2*)&C[(size_t)(row + 8) * Dn + col] =
            make_float2(tf32f(c[nt][2] + b0), tf32f(c[nt][3] + b1));
    }
}

// ---------------- fp32 FFMA tiled SGEMM (accuracy-critical logits) ----------------
#define BM 64
#define BNf 64
#define BKf 16

__global__ __launch_bounds__(256) void gemm_f32_kernel(
    const float* __restrict__ A, const float* __restrict__ W,
    const float* __restrict__ bias, float* __restrict__ C,
    int M, int N, int K)
{
    __shared__ float As[BKf][BM];
    __shared__ float Bs[BKf][BNf];
    int tid = threadIdx.x;
    int tx = tid & 15, ty = tid >> 4;
    int bm = blockIdx.y * BM, bn = blockIdx.x * BNf;

    float acc[4][4];
#pragma unroll
    for (int i = 0; i < 4; i++)
#pragma unroll
        for (int j = 0; j < 4; j++) acc[i][j] = 0.f;

    int a_row = tid >> 2;
    int a_col = (tid & 3) * 4;
    int b_row = tid >> 4;
    int b_col = (tid & 15) * 4;

    const float* Aptr = A + (size_t)(bm + a_row) * K + a_col;
    const float* Wptr = W + (size_t)b_row * N + bn + b_col;

    for (int kt = 0; kt < K; kt += BKf) {
        float4 av = *(const float4*)(Aptr + kt);
        As[a_col + 0][a_row] = av.x;
        As[a_col + 1][a_row] = av.y;
        As[a_col + 2][a_row] = av.z;
        As[a_col + 3][a_row] = av.w;
        float4 bv = *(const float4*)(Wptr + (size_t)kt * N);
        *(float4*)&Bs[b_row][b_col] = bv;
        __syncthreads();
#pragma unroll
        for (int kk = 0; kk < BKf; kk++) {
            float ar[4], br[4];
#pragma unroll
            for (int i = 0; i < 4; i++) ar[i] = As[kk][ty + 16 * i];
#pragma unroll
            for (int j = 0; j < 4; j++) br[j] = Bs[kk][tx + 16 * j];
#pragma unroll
            for (int i = 0; i < 4; i++)
#pragma unroll
                for (int j = 0; j < 4; j++) acc[i][j] += ar[i] * br[j];
        }
        __syncthreads();
    }

#pragma unroll
    for (int i = 0; i < 4; i++) {
        int row = bm + ty + 16 * i;
#pragma unroll
        for (int j = 0; j < 4; j++) {
            int col = bn + tx + 16 * j;
            C[(size_t)row * N + col] = acc[i][j] + bias[col];
        }
    }
}

// ---------------- concat ref/off/attw weights into padded [256,128] ----------------
__global__ void concat_w_kernel(
    const float* __restrict__ ref_w, const float* __restrict__ ref_b,
    const float* __restrict__ off_w, const float* __restrict__ off_b,
    const float* __restrict__ attw_w, const float* __restrict__ attw_b,
    float* __restrict__ Wc, float* __restrict__ bc)
{
    int i = blockIdx.x * 256 + threadIdx.x;
    if (i < Dn * 128) {
        int d = i >> 7, j = i & 127;
        float v = 0.f;
        if (j < 2) v = ref_w[d * 2 + j];
        else if (j < 66) v = off_w[d * 64 + (j - 2)];
        else if (j < 98) v = attw_w[d * 32 + (j - 66)];
        Wc[i] = v;
    }
    if (i < 128) {
        float v = 0.f;
        if (i < 2) v = ref_b[i];
        else if (i < 66) v = off_b[i - 2];
        else if (i < 98) v = attw_b[i - 66];
        bc[i] = v;
    }
}

// ---------------- flash self-attention: 2 queries/thread (R10 shape, cleaned) ------
#define KT 60

__global__ __launch_bounds__(160) void flash_kernel(
    const float* __restrict__ qkv, float* __restrict__ sa)
{
    __shared__ float4 Ks[KT][8];
    __shared__ float4 Vs[KT][8];

    const int bh = blockIdx.x;
    const int b = bh >> 3, h = bh & 7;
    const int tid = threadIdx.x;
    const int qi0 = tid;
    const int qi1 = tid + 160;
    const bool act1 = qi1 < Qn;

    ull q0[16], q1[16], a0[16], a1[16];
    const float* qp0 = qkv + (size_t)(b * Qn + qi0) * (3 * Dn) + h * DHn;
    const float* qp1 = qkv + (size_t)(b * Qn + (act1 ? qi1 : 0)) * (3 * Dn) + h * DHn;
#pragma unroll
    for (int i = 0; i < 8; i++) {
        F4U t0; t0.f = *(const float4*)(qp0 + i * 4);
        q0[2 * i] = t0.u[0]; q0[2 * i + 1] = t0.u[1];
        F4U t1; t1.f = *(const float4*)(qp1 + i * 4);
        q1[2 * i] = t1.u[0]; q1[2 * i + 1] = t1.u[1];
    }
#pragma unroll
    for (int i = 0; i < 16; i++) { a0[i] = 0ull; a1[i] = 0ull; }

    float su0 = 0.f, su1 = 0.f;
    const float scale = 0.17677669529663689f;

    const float* kbase = qkv + (size_t)(b * Qn) * (3 * Dn) + Dn + h * DHn;
    const float* vbase = kbase + Dn;

    for (int t0 = 0; t0 < Qn; t0 += KT) {
        for (int i = tid; i < KT * 8; i += 160) {
            int j = i >> 3, dc = i & 7;
            size_t off = (size_t)(t0 + j) * (3 * Dn) + dc * 4;
            Ks[j][dc] = *(const float4*)(kbase + off);
            Vs[j][dc] = *(const float4*)(vbase + off);
        }
        __syncthreads();

#pragma unroll 2
        for (int j = 0; j < KT; j++) {
            F4U w0; w0.f = Ks[j][0]; F4U w1; w1.f = Ks[j][1];
            F4U w2; w2.f = Ks[j][2]; F4U w3; w3.f = Ks[j][3];
            F4U w4; w4.f = Ks[j][4]; F4U w5; w5.f = Ks[j][5];
            F4U w6; w6.f = Ks[j][6]; F4U w7; w7.f = Ks[j][7];
            ull k2a[8] = { w0.u[0], w0.u[1], w1.u[0], w1.u[1],
                           w2.u[0], w2.u[1], w3.u[0], w3.u[1] };
            ull k2b[8] = { w4.u[0], w4.u[1], w5.u[0], w5.u[1],
                           w6.u[0], w6.u[1], w7.u[0], w7.u[1] };

            ull s0a = 0ull, s0b = 0ull, s1a = 0ull, s1b = 0ull;
#pragma unroll
            for (int i = 0; i < 8; i++) {
                s0a = fma2(q0[i], k2a[i], s0a);
                s1a = fma2(q1[i], k2a[i], s1a);
                s0b = fma2(q0[8 + i], k2b[i], s0b);
                s1b = fma2(q1[8 + i], k2b[i], s1b);
            }
            F2U u0a; u0a.u = s0a; F2U u0b; u0b.u = s0b;
            F2U u1a; u1a.u = s1a; F2U u1b; u1b.u = s1b;
            float s0 = (u0a.f.x + u0a.f.y + u0b.f.x + u0b.f.y) * scale;
            float s1 = (u1a.f.x + u1a.f.y + u1b.f.x + u1b.f.y) * scale;
            float p0 = __expf(s0);
            float p1 = __expf(s1);
            su0 += p0;
            su1 += p1;
            F2U pp0; pp0.f = make_float2(p0, p0);
            F2U pp1; pp1.f = make_float2(p1, p1);
            ull p02 = pp0.u, p12 = pp1.u;

            F4U v0; v0.f = Vs[j][0]; F4U v1; v1.f = Vs[j][1];
            F4U v2; v2.f = Vs[j][2]; F4U v3; v3.f = Vs[j][3];
            F4U v4; v4.f = Vs[j][4]; F4U v5; v5.f = Vs[j][5];
            F4U v6; v6.f = Vs[j][6]; F4U v7; v7.f = Vs[j][7];
            ull vv[16] = { v0.u[0], v0.u[1], v1.u[0], v1.u[1],
                           v2.u[0], v2.u[1], v3.u[0], v3.u[1],
                           v4.u[0], v4.u[1], v5.u[0], v5.u[1],
                           v6.u[0], v6.u[1], v7.u[0], v7.u[1] };
#pragma unroll
            for (int i = 0; i < 16; i++) {
                a0[i] = fma2(p02, vv[i], a0[i]);
                a1[i] = fma2(p12, vv[i], a1[i]);
            }
        }
        __syncthreads();
    }

    {
        float inv0 = 1.f / su0;
        float* op0 = sa + (size_t)(b * Qn + qi0) * Dn + h * DHn;
#pragma unroll
        for (int i = 0; i < 8; i++) {
            F2U lo; lo.u = a0[2 * i];
            F2U hi; hi.u = a0[2 * i + 1];
            float4 v = make_float4(tf32f(lo.f.x * inv0), tf32f(lo.f.y * inv0),
                                   tf32f(hi.f.x * inv0), tf32f(hi.f.y * inv0));
            *(float4*)(op0 + i * 4) = v;
        }
    }
    if (act1) {
        float inv1 = 1.f / su1;
        float* op1 = sa + (size_t)(b * Qn + qi1) * Dn + h * DHn;
#pragma unroll
        for (int i = 0; i < 8; i++) {
            F2U lo; lo.u = a1[2 * i];
            F2U hi; hi.u = a1[2 * i + 1];
            float4 v = make_float4(tf32f(lo.f.x * inv1), tf32f(lo.f.y * inv1),
                                   tf32f(hi.f.x * inv1), tf32f(hi.f.y * inv1));
            *(float4*)(op1 + i * 4) = v;
        }
    }
}

// ---------------- fused residual-add + LayerNorm (optional half 2nd out) ----------
__global__ void add_ln_kernel(const float* __restrict__ a, const float* __restrict__ r,
                              const float* __restrict__ g, const float* __restrict__ be,
                              float* __restrict__ out, __half* __restrict__ out_h)
{
    int row = blockIdx.x, t = threadIdx.x;
    size_t idx = (size_t)row * Dn + t;
    float v = a[idx] + r[idx];
    __shared__ float red[8];
    float s = v;
#pragma unroll
    for (int o = 16; o; o >>= 1) s += __shfl_xor_sync(~0u, s, o);
    if ((t & 31) == 0) red[t >> 5] = s;
    __syncthreads();
    float mean = 0.f;
#pragma unroll
    for (int i = 0; i < 8; i++) mean += red[i];
    mean *= (1.f / Dn);
    float d = v - mean;
    float s2 = d * d;
#pragma unroll
    for (int o = 16; o; o >>= 1) s2 += __shfl_xor_sync(~0u, s2, o);
    __syncthreads();
    if ((t & 31) == 0) red[t >> 5] = s2;
    __syncthreads();
    float var = 0.f;
#pragma unroll
    for (int i = 0; i < 8; i++) var += red[i];
    var *= (1.f / Dn);
    float o2 = d * rsqrtf(var + LN_EPS) * g[t] + be[t];
    out[idx] = o2;
    if (out_h) out_h[idx] = __float2half(o2);
}

// ---------------- sampler2: weights + bilinear gather of RAW memory -> m_eff ------
__global__ __launch_bounds__(256) void sampler2_kernel(
    const float* __restrict__ lgbuf, const float* __restrict__ memory,
    float* __restrict__ me)
{
    __shared__ float lg[128];
    __shared__ float sref[2];
    __shared__ float swts[Hn * Pn];
    __shared__ int   srow[128];
    __shared__ float swt[128];

    int bq = blockIdx.x;
    int b = bq / Qn;
    int t = threadIdx.x;

    if (t < 128) lg[t] = lgbuf[(size_t)bq * 128 + t];
    __syncthreads();

    if (t < 2) sref[t] = 1.f / (1.f + expf(-lg[t]));
    else if (t >= 32 && t < 40) {
        int h = t - 32;
        const float* al = &lg[66 + h * 4];
        float m = fmaxf(fmaxf(al[0], al[1]), fmaxf(al[2], al[3]));
        float e0 = expf(al[0]-m), e1 = expf(al[1]-m), e2 = expf(al[2]-m), e3 = expf(al[3]-m);
        float inv = 1.f / (e0 + e1 + e2 + e3);
        swts[h*4+0] = e0*inv; swts[h*4+1] = e1*inv; swts[h*4+2] = e2*inv; swts[h*4+3] = e3*inv;
    }
    __syncthreads();

    if (t < 32) {
        int h = t >> 2, p = t & 3;
        float lx = fminf(fmaxf(sref[0] + lg[2 + h * 8 + p * 2 + 0], 0.f), 1.f);
        float ly = fminf(fmaxf(sref[1] + lg[2 + h * 8 + p * 2 + 1], 0.f), 1.f);
        float sx = lx * (float)(WGn - 1);
        float sy = ly * (float)(HGn - 1);
        float x0f = floorf(sx), y0f = floorf(sy);
        int x0 = min(max((int)x0f, 0), WGn - 1);
        int y0 = min(max((int)y0f, 0), HGn - 1);
        int x1i = min(x0 + 1, WGn - 1);
        int y1i = min(y0 + 1, HGn - 1);
        float wx1 = sx - x0f, wx0 = 1.f - wx1;
        float wy1 = sy - y0f, wy0 = 1.f - wy1;
        float wp = swts[t];
        int rowb = b * HWn;
        int base = t * 4;
        srow[base + 0] = rowb + y0  * WGn + x0;  swt[base + 0] = wp * wx0 * wy0;
        srow[base + 1] = rowb + y1i * WGn + x0;  swt[base + 1] = wp * wx0 * wy1;
        srow[base + 2] = rowb + y0  * WGn + x1i; swt[base + 2] = wp * wx1 * wy0;
        srow[base + 3] = rowb + y1i * WGn + x1i; swt[base + 3] = wp * wx1 * wy1;
    }
    __syncthreads();

#pragma unroll
    for (int h = 0; h < Hn; h++) {
        float acc = 0.f;
#pragma unroll
        for (int i = 0; i < 16; i++)
            acc += swt[h * 16 + i] * memory[(size_t)srow[h * 16 + i] * Dn + t];
        me[((size_t)h * BQ + bq) * Dn + t] = tf32f(acc);
    }
}

// ---------------- launch ----------------
extern "C" void kernel_launch(void* const* d_in, const int* in_sizes, int n_in,
                              void* d_out, int out_size)
{
    const float* tgt        = (const float*)d_in[0];
    const float* memory     = (const float*)d_in[1];
    const float* in_proj_w  = (const float*)d_in[2];
    const float* in_proj_b  = (const float*)d_in[3];
    const float* out_proj_w = (const float*)d_in[4];
    const float* out_proj_b = (const float*)d_in[5];
    const float* norm1_g    = (const float*)d_in[6];
    const float* norm1_b    = (const float*)d_in[7];
    const float* ref_w      = (const float*)d_in[8];
    const float* ref_b      = (const float*)d_in[9];
    const float* off_w      = (const float*)d_in[10];
    const float* off_b      = (const float*)d_in[11];
    const float* attw_w     = (const float*)d_in[12];
    const float* attw_b     = (const float*)d_in[13];
    const float* vproj_w    = (const float*)d_in[14];
    const float* vproj_b    = (const float*)d_in[15];
    const float* oproj_w    = (const float*)d_in[16];
    const float* oproj_b    = (const float*)d_in[17];
    const float* norm2_g    = (const float*)d_in[18];
    const float* norm2_b    = (const float*)d_in[19];
    const float* lin1_w     = (const float*)d_in[20];
    const float* lin1_b     = (const float*)d_in[21];
    const float* lin2_w     = (const float*)d_in[22];
    const float* lin2_b     = (const float*)d_in[23];
    const float* norm3_g    = (const float*)d_in[24];
    const float* norm3_b    = (const float*)d_in[25];
    float* out = (float*)d_out;

    float *qkv, *sa, *x1, *x2, *tmp, *ca, *me, *wcat, *bcat, *lgb;
    float *ipw, *opw, *vpw, *oqw, *tgtr;
    __half *x2h, *ffh;
    uint32_t *p1w, *p2w;
    cudaGetSymbolAddress((void**)&qkv,  g_qkv);
    cudaGetSymbolAddress((void**)&sa,   g_sa);
    cudaGetSymbolAddress((void**)&x1,   g_x1);
    cudaGetSymbolAddress((void**)&x2,   g_x2);
    cudaGetSymbolAddress((void**)&x2h,  g_x2h);
    cudaGetSymbolAddress((void**)&tmp,  g_tmp);
    cudaGetSymbolAddress((void**)&ca,   g_ca);
    cudaGetSymbolAddress((void**)&me,   g_me);
    cudaGetSymbolAddress((void**)&ffh,  g_ffh);
    cudaGetSymbolAddress((void**)&wcat, g_wcat);
    cudaGetSymbolAddress((void**)&bcat, g_bcat);
    cudaGetSymbolAddress((void**)&lgb,  g_lg);
    cudaGetSymbolAddress((void**)&ipw,  g_ipw);
    cudaGetSymbolAddress((void**)&opw,  g_opw);
    cudaGetSymbolAddress((void**)&vpw,  g_vpw);
    cudaGetSymbolAddress((void**)&oqw,  g_oqw);
    cudaGetSymbolAddress((void**)&tgtr, g_tgtr);
    cudaGetSymbolAddress((void**)&p1w,  g_p1w);
    cudaGetSymbolAddress((void**)&p2w,  g_p2w);

    const int smem1 = (3 * 64 * APITCH + 3 * TBK * BPITCH) * 4;   // 41472
    const int smemh = (3 * 64 * HAP + 3 * 16 * BPITCH) * 4;       // 41472
    cudaFuncSetAttribute((const void*)gemm_tf32_async, cudaFuncAttributeMaxDynamicSharedMemorySize, smem1);
    cudaFuncSetAttribute((const void*)gemm_fp16_async, cudaFuncAttributeMaxDynamicSharedMemorySize, smemh);

    // 0. pre-round tf32 weights + tgt; pack FFN weights fp16; concat logits weights
    round5_kernel<<<1584, 256>>>(
        (const float4*)in_proj_w, (const float4*)out_proj_w, (const float4*)vproj_w,
        (const float4*)oproj_w, (const float4*)tgt,
        (float4*)ipw, (float4*)opw, (float4*)vpw, (float4*)oqw, (float4*)tgtr);
    packh_kernel<<<1024, 256>>>(lin1_w, lin2_w, p1w, p2w);
    concat_w_kernel<<<128, 256>>>(ref_w, ref_b, off_w, off_b, attw_w, attw_b, wcat, bcat);
    // 1. qkv projection [4800,256]@[256,768]
    gemm_tf32_async<<<dim3(768 / TBN, BQ / 64), 256, smem1>>>(tgtr, ipw, in_proj_b, qkv, BQ, 768, Dn, 0, 0);
    // 2. fused self-attention (2 queries/thread)
    flash_kernel<<<Bn * Hn, 160>>>(qkv, sa);
    // 3. out_proj
    gemm_tf32_async<<<dim3(Dn / TBN, BQ / 64), 256, smem1>>>(sa, opw, out_proj_b, tmp, BQ, Dn, Dn, 0, 0);
    // 4. x1 = LN(tgt + sa_out)
    add_ln_kernel<<<BQ, Dn>>>(tgt, tmp, norm1_g, norm1_b, x1, nullptr);
    // 5. logits — fp32 (accuracy-critical)
    gemm_f32_kernel<<<dim3(128 / BNf, BQ / BM), 256>>>(x1, wcat, bcat, lgb, BQ, 128, Dn);
    // 6. sampler2: gather raw memory into per-head effective vectors
    sampler2_kernel<<<BQ, 256>>>(lgb, memory, me);
    // 7. per-head projection: ca = m_eff @ vproj_w (+bias)
    gemm_proj<<<dim3(Hn, BQ / 64), 128>>>(me, vpw, vproj_b, ca);
    // 8. oproj
    gemm_tf32_async<<<dim3(Dn / TBN, BQ / 64), 256, smem1>>>(ca, oqw, oproj_b, tmp, BQ, Dn, Dn, 0, 0);
    // 9. x2 = LN(x1 + ca_out); x2h = half(x2)
    add_ln_kernel<<<BQ, Dn>>>(x1, tmp, norm2_g, norm2_b, x2, x2h);
    // 10. FFN lin1 + ReLU — fp16 tensor cores, half output
    gemm_fp16_async<<<dim3(Fn / TBN, BQ / 64), 256, smemh>>>(x2h, p1w, lin1_b, ffh, BQ, Fn, Dn, 1, 1);
    // 11. FFN lin2 — fp16 tensor cores, fp32 output
    gemm_fp16_async<<<dim3(Dn / TBN, BQ / 64), 256, smemh>>>(ffh, p2w, lin2_b, tmp, BQ, Dn, Fn, 0, 0);
    // 12. out = LN(x2 + ffn)
    add_ln_kernel<<<BQ, Dn>>>(x2, tmp, norm3_g, norm3_b, out, nullptr);
}

// round 14
// speedup vs baseline: 1.2481x; 1.0596x over previous
#include <cuda_runtime.h>
#include <cuda_fp16.h>
#include <math.h>
#include <stdint.h>

#define Bn 16
#define Qn 300
#define Dn 256
#define Hn 8
#define Pn 4
#define Fn 2048
#define HGn 100
#define WGn 100
#define HWn 10000
#define DHn 32
#define LN_EPS 1e-5f

#define BQ (Bn*Qn)            // 4800
#define MEMROWS (Bn*HWn)      // 160000

typedef unsigned long long ull;

// ---------------- scratch (allocation-free: __device__ globals) ----------------
__device__ float  g_qkv[BQ*3*Dn];
__device__ __half g_sah[BQ*Dn];
__device__ float  g_x1[BQ*Dn];
__device__ float  g_x2[BQ*Dn];
__device__ __half g_x2h[BQ*Dn];
__device__ float  g_tmp[BQ*Dn];
__device__ __half g_cah[BQ*Dn];
__device__ __half g_meh[Hn*BQ*Dn];
__device__ __half g_ffh[BQ*Fn];
__device__ float  g_wcat[Dn*128];
__device__ float  g_bcat[128];
__device__ float  g_lg[BQ*128];
__device__ __half g_tgth[BQ*Dn];
// fp16 k-pair-packed weights
__device__ uint32_t g_pip[(Dn/2)*768];  // in_proj
__device__ uint32_t g_pop[(Dn/2)*Dn];   // out_proj
__device__ uint32_t g_poq[(Dn/2)*Dn];   // oproj
__device__ uint32_t g_pvp[(Dn/2)*Dn];   // vproj
__device__ uint32_t g_p1w[(Dn/2)*Fn];   // lin1
__device__ uint32_t g_p2w[(Fn/2)*Dn];   // lin2

__device__ __forceinline__ ull fma2(ull a, ull b, ull c) {
    ull d;
    asm("fma.rn.f32x2 %0, %1, %2, %3;" : "=l"(d) : "l"(a), "l"(b), "l"(c));
    return d;
}

union F4U { float4 f; ull u[2]; };
union F2U { float2 f; ull u; };

// ---------------- pack all weights into fp16 k-pair half2 ----------------
// dest u32 blocks of 256: ip 384 | op 128 | oq 128 | vp 128 | p1 1024 | p2 1024
__global__ void packw_kernel(
    const float* __restrict__ ipw, const float* __restrict__ opw,
    const float* __restrict__ oqw, const float* __restrict__ vpw,
    const float* __restrict__ l1w, const float* __restrict__ l2w,
    uint32_t* __restrict__ pip, uint32_t* __restrict__ pop,
    uint32_t* __restrict__ poq, uint32_t* __restrict__ pvp,
    uint32_t* __restrict__ p1,  uint32_t* __restrict__ p2)
{
    int bi = blockIdx.x;
    const float* s; uint32_t* d; int N; int base;
    if      (bi <  384) { s = ipw; d = pip; N = 768;  base = bi; }
    else if (bi <  512) { s = opw; d = pop; N = Dn;   base = bi - 384; }
    else if (bi <  640) { s = oqw; d = poq; N = Dn;   base = bi - 512; }
    else if (bi <  768) { s = vpw; d = pvp; N = Dn;   base = bi - 640; }
    else if (bi < 1792) { s = l1w; d = p1;  N = Fn;   base = bi - 768; }
    else                { s = l2w; d = p2;  N = Dn;   base = bi - 1792; }
    int i = base * 256 + threadIdx.x;
    int k2 = i / N, n = i - k2 * N;
    __half2 h = __floats2half2_rn(s[(size_t)(2*k2) * N + n], s[(size_t)(2*k2+1) * N + n]);
    d[i] = *(uint32_t*)&h;
}

// ---------------- convert tgt to half ----------------
__global__ void tgth_kernel(const float4* __restrict__ src, __half2* __restrict__ dst)
{
    int i = blockIdx.x * 256 + threadIdx.x;   // over BQ*Dn/4
    float4 v = src[i];
    dst[2*i]   = __floats2half2_rn(v.x, v.y);
    dst[2*i+1] = __floats2half2_rn(v.z, v.w);
}

// ---------------- common constants ----------------
#define TBN 128
#define BPITCH (TBN + 8)    // 136
#define HBK 32
#define HAP 20

__device__ __forceinline__ void cp16(void* dst, const void* src) {
    uint32_t d = (uint32_t)__cvta_generic_to_shared(dst);
    asm volatile("cp.async.ca.shared.global [%0], [%1], 16;" :: "r"(d), "l"(src));
}

#define MMA_F16(c, a, b) \
    asm volatile( \
        "mma.sync.aligned.m16n8k16.row.col.f32.f16.f16.f32 " \
        "{%0,%1,%2,%3}, {%4,%5,%6,%7}, {%8,%9}, {%0,%1,%2,%3};" \
        : "+f"((c)[0]), "+f"((c)[1]), "+f"((c)[2]), "+f"((c)[3]) \
        : "r"((a)[0]), "r"((a)[1]), "r"((a)[2]), "r"((a)[3]), \
          "r"((b)[0]), "r"((b)[1]))

// ---------------- fp16 64x128 GEMM (m16n8k16), 3-stage cp.async --------------------
// A: half row-major [M][K]; Wpk: k-pair-packed half2 [K/2][N]; TBK=32.
__global__ __launch_bounds__(256) void gemm_fp16_async(
    const __half* __restrict__ A, const uint32_t* __restrict__ Wpk,
    const float* __restrict__ bias, void* __restrict__ Cout,
    int M, int N, int K, int relu, int outhalf)
{
    extern __shared__ uint32_t smemu[];
    uint32_t (*As)[64][HAP]    = (uint32_t(*)[64][HAP])smemu;
    uint32_t (*Bs)[16][BPITCH] = (uint32_t(*)[16][BPITCH])(smemu + 3 * 64 * HAP);

    const int tid  = threadIdx.x;
    const int lane = tid & 31;
    const int warp = tid >> 5;
    const int wm = (warp >> 2) * 32;
    const int wn = (warp & 3) * 32;
    const int bm = blockIdx.y * 64;
    const int bn = blockIdx.x * TBN;

    const int lq = lane >> 2;
    const int lr = lane & 3;

    const int a_row = tid >> 2;
    const int a_u32 = (tid & 3) * 4;
    const int b_row = tid >> 4;
    const int b_u32 = (tid & 15) * 8;

    const __half* Aptr = A + (size_t)(bm + a_row) * K + a_u32 * 2;
    const uint32_t* Wptr = Wpk + (size_t)b_row * N + bn + b_u32;

    float c[2][4][4];
#pragma unroll
    for (int i = 0; i < 2; i++)
#pragma unroll
        for (int j = 0; j < 4; j++)
#pragma unroll
            for (int l = 0; l < 4; l++) c[i][j][l] = 0.f;

    const int nk = K / HBK;

#pragma unroll
    for (int s = 0; s < 2; s++) {
        int kt = s * HBK;
        cp16(&As[s][a_row][a_u32], Aptr + kt);
        cp16(&Bs[s][b_row][b_u32],     Wptr + (size_t)(kt / 2) * N);
        cp16(&Bs[s][b_row][b_u32 + 4], Wptr + (size_t)(kt / 2) * N + 4);
        asm volatile("cp.async.commit_group;" ::: "memory");
    }

    for (int it = 0; it < nk; it++) {
        asm volatile("cp.async.wait_group 1;" ::: "memory");
        __syncthreads();

        int nxt = it + 2;
        if (nxt < nk) {
            int s = nxt % 3;
            int kt = nxt * HBK;
            cp16(&As[s][a_row][a_u32], Aptr + kt);
            cp16(&Bs[s][b_row][b_u32],     Wptr + (size_t)(kt / 2) * N);
            cp16(&Bs[s][b_row][b_u32 + 4], Wptr + (size_t)(kt / 2) * N + 4);
        }
        asm volatile("cp.async.commit_group;" ::: "memory");

        const int buf = it % 3;
#pragma unroll
        for (int ks2 = 0; ks2 < 16; ks2 += 8) {
            uint32_t a[2][4], b[4][2];
#pragma unroll
            for (int mt = 0; mt < 2; mt++) {
                int mr = wm + mt * 16 + lq;
                a[mt][0] = As[buf][mr    ][ks2 + lr];
                a[mt][1] = As[buf][mr + 8][ks2 + lr];
                a[mt][2] = As[buf][mr    ][ks2 + lr + 4];
                a[mt][3] = As[buf][mr + 8][ks2 + lr + 4];
            }
#pragma unroll
            for (int nt = 0; nt < 4; nt++) {
                int nc = wn + nt * 8 + lq;
                b[nt][0] = Bs[buf][ks2 + lr    ][nc];
                b[nt][1] = Bs[buf][ks2 + lr + 4][nc];
            }
#pragma unroll
            for (int mt = 0; mt < 2; mt++)
#pragma unroll
                for (int nt = 0; nt < 4; nt++)
                    MMA_F16(c[mt][nt], a[mt], b[nt]);
        }
    }

#pragma unroll
    for (int mt = 0; mt < 2; mt++) {
#pragma unroll
        for (int nt = 0; nt < 4; nt++) {
            int row = bm + wm + mt * 16 + lq;
            int col = bn + wn + nt * 8 + lr * 2;
            float b0 = bias[col], b1 = bias[col + 1];
            float v0 = c[mt][nt][0] + b0;
            float v1 = c[mt][nt][1] + b1;
            float v2 = c[mt][nt][2] + b0;
            float v3 = c[mt][nt][3] + b1;
            if (relu) {
                v0 = fmaxf(v0, 0.f); v1 = fmaxf(v1, 0.f);
                v2 = fmaxf(v2, 0.f); v3 = fmaxf(v3, 0.f);
            }
            if (outhalf) {
                __half* C = (__half*)Cout;
                *(__half2*)&C[(size_t)row * N + col]       = __floats2half2_rn(v0, v1);
                *(__half2*)&C[(size_t)(row + 8) * N + col] = __floats2half2_rn(v2, v3);
            } else {
                float* C = (float*)Cout;
                *(float2*)&C[(size_t)row * N + col]       = make_float2(v0, v1);
                *(float2*)&C[(size_t)(row + 8) * N + col] = make_float2(v2, v3);
            }
        }
    }
}

// ---------------- fp16 per-head projection: [4800,256]@[256,32] x 8 heads ----------
__global__ __launch_bounds__(128) void gemm_proj_h(
    const __half* __restrict__ A, const uint32_t* __restrict__ Wpk,
    const float* __restrict__ bias, __half* __restrict__ C)
{
    __shared__ uint32_t As[3][64][HAP];
    __shared__ uint32_t Bs[3][16][36];

    const int h  = blockIdx.x;       // 0..7
    const int bm = blockIdx.y * 64;
    const int t  = threadIdx.x;      // 0..127
    const int lane = t & 31;
    const int warp = t >> 5;
    const int wm = warp * 16;
    const int lq = lane >> 2;
    const int lr = lane & 3;

    const int a_row = t >> 1;          // 0..63
    const int a_u32 = (t & 1) * 8;     // 0 or 8
    const int b_row = t >> 3;          // 0..15
    const int b_col = (t & 7) * 4;     // 0..28

    const __half* Aptr = A + ((size_t)h * BQ + bm + a_row) * Dn + a_u32 * 2;
    const uint32_t* Wptr = Wpk + (size_t)b_row * Dn + h * 32 + b_col;

    float c[4][4];
#pragma unroll
    for (int j = 0; j < 4; j++)
#pragma unroll
        for (int l = 0; l < 4; l++) c[j][l] = 0.f;

    const int nk = Dn / HBK;  // 8

#pragma unroll
    for (int s = 0; s < 2; s++) {
        int kt = s * HBK;
        cp16(&As[s][a_row][a_u32],     Aptr + kt);
        cp16(&As[s][a_row][a_u32 + 4], Aptr + kt + 8);
        cp16(&Bs[s][b_row][b_col],     Wptr + (size_t)(kt / 2) * Dn);
        asm volatile("cp.async.commit_group;" ::: "memory");
    }

    for (int it = 0; it < nk; it++) {
        asm volatile("cp.async.wait_group 1;" ::: "memory");
        __syncthreads();

        int nxt = it + 2;
        if (nxt < nk) {
            int s = nxt % 3;
            int kt = nxt * HBK;
            cp16(&As[s][a_row][a_u32],     Aptr + kt);
            cp16(&As[s][a_row][a_u32 + 4], Aptr + kt + 8);
            cp16(&Bs[s][b_row][b_col],     Wptr + (size_t)(kt / 2) * Dn);
        }
        asm volatile("cp.async.commit_group;" ::: "memory");

        const int buf = it % 3;
#pragma unroll
        for (int ks2 = 0; ks2 < 16; ks2 += 8) {
            uint32_t a[4], b[4][2];
            int mr = wm + lq;
            a[0] = As[buf][mr    ][ks2 + lr];
            a[1] = As[buf][mr + 8][ks2 + lr];
            a[2] = As[buf][mr    ][ks2 + lr + 4];
            a[3] = As[buf][mr + 8][ks2 + lr + 4];
#pragma unroll
            for (int nt = 0; nt < 4; nt++) {
                int nc = nt * 8 + lq;
                b[nt][0] = Bs[buf][ks2 + lr    ][nc];
                b[nt][1] = Bs[buf][ks2 + lr + 4][nc];
            }
#pragma unroll
            for (int nt = 0; nt < 4; nt++)
                MMA_F16(c[nt], a, b[nt]);
        }
    }

#pragma unroll
    for (int nt = 0; nt < 4; nt++) {
        int row = bm + wm + lq;
        int col = h * 32 + nt * 8 + lr * 2;
        float b0 = bias[col], b1 = bias[col + 1];
        *(__half2*)&C[(size_t)row * Dn + col]       = __floats2half2_rn(c[nt][0] + b0, c[nt][1] + b1);
        *(__half2*)&C[(size_t)(row + 8) * Dn + col] = __floats2half2_rn(c[nt][2] + b0, c[nt][3] + b1);
    }
}

// ---------------- fp32 FFMA tiled SGEMM (accuracy-critical logits) ----------------
#define BM 64
#define BNf 64
#define BKf 16

__global__ __launch_bounds__(256) void gemm_f32_kernel(
    const float* __restrict__ A, const float* __restrict__ W,
    const float* __restrict__ bias, float* __restrict__ C,
    int M, int N, int K)
{
    __shared__ float As[BKf][BM];
    __shared__ float Bs[BKf][BNf];
    int tid = threadIdx.x;
    int tx = tid & 15, ty = tid >> 4;
    int bm = blockIdx.y * BM, bn = blockIdx.x * BNf;

    float acc[4][4];
#pragma unroll
    for (int i = 0; i < 4; i++)
#pragma unroll
        for (int j = 0; j < 4; j++) acc[i][j] = 0.f;

    int a_row = tid >> 2;
    int a_col = (tid & 3) * 4;
    int b_row = tid >> 4;
    int b_col = (tid & 15) * 4;

    const float* Aptr = A + (size_t)(bm + a_row) * K + a_col;
    const float* Wptr = W + (size_t)b_row * N + bn + b_col;

    for (int kt = 0; kt < K; kt += BKf) {
        float4 av = *(const float4*)(Aptr + kt);
        As[a_col + 0][a_row] = av.x;
        As[a_col + 1][a_row] = av.y;
        As[a_col + 2][a_row] = av.z;
        As[a_col + 3][a_row] = av.w;
        float4 bv = *(const float4*)(Wptr + (size_t)kt * N);
        *(float4*)&Bs[b_row][b_col] = bv;
        __syncthreads();
#pragma unroll
        for (int kk = 0; kk < BKf; kk++) {
            float ar[4], br[4];
#pragma unroll
            for (int i = 0; i < 4; i++) ar[i] = As[kk][ty + 16 * i];
#pragma unroll
            for (int j = 0; j < 4; j++) br[j] = Bs[kk][tx + 16 * j];
#pragma unroll
            for (int i = 0; i < 4; i++)
#pragma unroll
                for (int j = 0; j < 4; j++) acc[i][j] += ar[i] * br[j];
        }
        __syncthreads();
    }

#pragma unroll
    for (int i = 0; i < 4; i++) {
        int row = bm + ty + 16 * i;
#pragma unroll
        for (int j = 0; j < 4; j++) {
            int col = bn + tx + 16 * j;
            C[(size_t)row * N + col] = acc[i][j] + bias[col];
        }
    }
}

// ---------------- concat ref/off/attw weights into padded [256,128] ----------------
__global__ void concat_w_kernel(
    const float* __restrict__ ref_w, const float* __restrict__ ref_b,
    const float* __restrict__ off_w, const float* __restrict__ off_b,
    const float* __restrict__ attw_w, const float* __restrict__ attw_b,
    float* __restrict__ Wc, float* __restrict__ bc)
{
    int i = blockIdx.x * 256 + threadIdx.x;
    if (i < Dn * 128) {
        int d = i >> 7, j = i & 127;
        float v = 0.f;
        if (j < 2) v = ref_w[d * 2 + j];
        else if (j < 66) v = off_w[d * 64 + (j - 2)];
        else if (j < 98) v = attw_w[d * 32 + (j - 66)];
        Wc[i] = v;
    }
    if (i < 128) {
        float v = 0.f;
        if (i < 2) v = ref_b[i];
        else if (i < 66) v = off_b[i - 2];
        else if (i < 98) v = attw_b[i - 66];
        bc[i] = v;
    }
}

// ---------------- flash self-attention: 2 queries/thread, half output -------------
#define KT 60

__global__ __launch_bounds__(160) void flash_kernel(
    const float* __restrict__ qkv, __half* __restrict__ sa)
{
    __shared__ float4 Ks[KT][8];
    __shared__ float4 Vs[KT][8];

    const int bh = blockIdx.x;
    const int b = bh >> 3, h = bh & 7;
    const int tid = threadIdx.x;
    const int qi0 = tid;
    const int qi1 = tid + 160;
    const bool act1 = qi1 < Qn;

    ull q0[16], q1[16], a0[16], a1[16];
    const float* qp0 = qkv + (size_t)(b * Qn + qi0) * (3 * Dn) + h * DHn;
    const float* qp1 = qkv + (size_t)(b * Qn + (act1 ? qi1 : 0)) * (3 * Dn) + h * DHn;
#pragma unroll
    for (int i = 0; i < 8; i++) {
        F4U t0; t0.f = *(const float4*)(qp0 + i * 4);
        q0[2 * i] = t0.u[0]; q0[2 * i + 1] = t0.u[1];
        F4U t1; t1.f = *(const float4*)(qp1 + i * 4);
        q1[2 * i] = t1.u[0]; q1[2 * i + 1] = t1.u[1];
    }
#pragma unroll
    for (int i = 0; i < 16; i++) { a0[i] = 0ull; a1[i] = 0ull; }

    float su0 = 0.f, su1 = 0.f;
    const float scale = 0.17677669529663689f;

    const float* kbase = qkv + (size_t)(b * Qn) * (3 * Dn) + Dn + h * DHn;
    const float* vbase = kbase + Dn;

    for (int t0 = 0; t0 < Qn; t0 += KT) {
        for (int i = tid; i < KT * 8; i += 160) {
            int j = i >> 3, dc = i & 7;
            size_t off = (size_t)(t0 + j) * (3 * Dn) + dc * 4;
            Ks[j][dc] = *(const float4*)(kbase + off);
            Vs[j][dc] = *(const float4*)(vbase + off);
        }
        __syncthreads();

#pragma unroll 2
        for (int j = 0; j < KT; j++) {
            F4U w0; w0.f = Ks[j][0]; F4U w1; w1.f = Ks[j][1];
            F4U w2; w2.f = Ks[j][2]; F4U w3; w3.f = Ks[j][3];
            F4U w4; w4.f = Ks[j][4]; F4U w5; w5.f = Ks[j][5];
            F4U w6; w6.f = Ks[j][6]; F4U w7; w7.f = Ks[j][7];
            ull k2a[8] = { w0.u[0], w0.u[1], w1.u[0], w1.u[1],
                           w2.u[0], w2.u[1], w3.u[0], w3.u[1] };
            ull k2b[8] = { w4.u[0], w4.u[1], w5.u[0], w5.u[1],
                           w6.u[0], w6.u[1], w7.u[0], w7.u[1] };

            ull s0a = 0ull, s0b = 0ull, s1a = 0ull, s1b = 0ull;
#pragma unroll
            for (int i = 0; i < 8; i++) {
                s0a = fma2(q0[i], k2a[i], s0a);
                s1a = fma2(q1[i], k2a[i], s1a);
                s0b = fma2(q0[8 + i], k2b[i], s0b);
                s1b = fma2(q1[8 + i], k2b[i], s1b);
            }
            F2U u0a; u0a.u = s0a; F2U u0b; u0b.u = s0b;
            F2U u1a; u1a.u = s1a; F2U u1b; u1b.u = s1b;
            float s0 = (u0a.f.x + u0a.f.y + u0b.f.x + u0b.f.y) * scale;
            float s1 = (u1a.f.x + u1a.f.y + u1b.f.x + u1b.f.y) * scale;
            float p0 = __expf(s0);
            float p1 = __expf(s1);
            su0 += p0;
            su1 += p1;
            F2U pp0; pp0.f = make_float2(p0, p0);
            F2U pp1; pp1.f = make_float2(p1, p1);
            ull p02 = pp0.u, p12 = pp1.u;

            F4U v0; v0.f = Vs[j][0]; F4U v1; v1.f = Vs[j][1];
            F4U v2; v2.f = Vs[j][2]; F4U v3; v3.f = Vs[j][3];
            F4U v4; v4.f = Vs[j][4]; F4U v5; v5.f = Vs[j][5];
            F4U v6; v6.f = Vs[j][6]; F4U v7; v7.f = Vs[j][7];
            ull vv[16] = { v0.u[0], v0.u[1], v1.u[0], v1.u[1],
                           v2.u[0], v2.u[1], v3.u[0], v3.u[1],
                           v4.u[0], v4.u[1], v5.u[0], v5.u[1],
                           v6.u[0], v6.u[1], v7.u[0], v7.u[1] };
#pragma unroll
            for (int i = 0; i < 16; i++) {
                a0[i] = fma2(p02, vv[i], a0[i]);
                a1[i] = fma2(p12, vv[i], a1[i]);
            }
        }
        __syncthreads();
    }

    {
        float inv0 = 1.f / su0;
        __half* op0 = sa + (size_t)(b * Qn + qi0) * Dn + h * DHn;
#pragma unroll
        for (int i = 0; i < 8; i++) {
            F2U lo; lo.u = a0[2 * i];
            F2U hi; hi.u = a0[2 * i + 1];
            *(__half2*)(op0 + i * 4)     = __floats2half2_rn(lo.f.x * inv0, lo.f.y * inv0);
            *(__half2*)(op0 + i * 4 + 2) = __floats2half2_rn(hi.f.x * inv0, hi.f.y * inv0);
        }
    }
    if (act1) {
        float inv1 = 1.f / su1;
        __half* op1 = sa + (size_t)(b * Qn + qi1) * Dn + h * DHn;
#pragma unroll
        for (int i = 0; i < 8; i++) {
            F2U lo; lo.u = a1[2 * i];
            F2U hi; hi.u = a1[2 * i + 1];
            *(__half2*)(op1 + i * 4)     = __floats2half2_rn(lo.f.x * inv1, lo.f.y * inv1);
            *(__half2*)(op1 + i * 4 + 2) = __floats2half2_rn(hi.f.x * inv1, hi.f.y * inv1);
        }
    }
}

// ---------------- fused residual-add + LayerNorm (optional half 2nd out) ----------
__global__ void add_ln_kernel(const float* __restrict__ a, const float* __restrict__ r,
                              const float* __restrict__ g, const float* __restrict__ be,
                              float* __restrict__ out, __half* __restrict__ out_h)
{
    int row = blockIdx.x, t = threadIdx.x;
    size_t idx = (size_t)row * Dn + t;
    float v = a[idx] + r[idx];
    __shared__ float red[8];
    float s = v;
#pragma unroll
    for (int o = 16; o; o >>= 1) s += __shfl_xor_sync(~0u, s, o);
    if ((t & 31) == 0) red[t >> 5] = s;
    __syncthreads();
    float mean = 0.f;
#pragma unroll
    for (int i = 0; i < 8; i++) mean += red[i];
    mean *= (1.f / Dn);
    float d = v - mean;
    float s2 = d * d;
#pragma unroll
    for (int o = 16; o; o >>= 1) s2 += __shfl_xor_sync(~0u, s2, o);
    __syncthreads();
    if ((t & 31) == 0) red[t >> 5] = s2;
    __syncthreads();
    float var = 0.f;
#pragma unroll
    for (int i = 0; i < 8; i++) var += red[i];
    var *= (1.f / Dn);
    float o2 = d * rsqrtf(var + LN_EPS) * g[t] + be[t];
    out[idx] = o2;
    if (out_h) out_h[idx] = __float2half(o2);
}

// ---------------- sampler2: weights + bilinear gather of RAW memory -> m_eff (half)
__global__ __launch_bounds__(256) void sampler2_kernel(
    const float* __restrict__ lgbuf, const float* __restrict__ memory,
    __half* __restrict__ me)
{
    __shared__ float lg[128];
    __shared__ float sref[2];
    __shared__ float swts[Hn * Pn];
    __shared__ int   srow[128];
    __shared__ float swt[128];

    int bq = blockIdx.x;
    int b = bq / Qn;
    int t = threadIdx.x;

    if (t < 128) lg[t] = lgbuf[(size_t)bq * 128 + t];
    __syncthreads();

    if (t < 2) sref[t] = 1.f / (1.f + expf(-lg[t]));
    else if (t >= 32 && t < 40) {
        int h = t - 32;
        const float* al = &lg[66 + h * 4];
        float m = fmaxf(fmaxf(al[0], al[1]), fmaxf(al[2], al[3]));
        float e0 = expf(al[0]-m), e1 = expf(al[1]-m), e2 = expf(al[2]-m), e3 = expf(al[3]-m);
        float inv = 1.f / (e0 + e1 + e2 + e3);
        swts[h*4+0] = e0*inv; swts[h*4+1] = e1*inv; swts[h*4+2] = e2*inv; swts[h*4+3] = e3*inv;
    }
    __syncthreads();

    if (t < 32) {
        int h = t >> 2, p = t & 3;
        float lx = fminf(fmaxf(sref[0] + lg[2 + h * 8 + p * 2 + 0], 0.f), 1.f);
        float ly = fminf(fmaxf(sref[1] + lg[2 + h * 8 + p * 2 + 1], 0.f), 1.f);
        float sx = lx * (float)(WGn - 1);
        float sy = ly * (float)(HGn - 1);
        float x0f = floorf(sx), y0f = floorf(sy);
        int x0 = min(max((int)x0f, 0), WGn - 1);
        int y0 = min(max((int)y0f, 0), HGn - 1);
        int x1i = min(x0 + 1, WGn - 1);
        int y1i = min(y0 + 1, HGn - 1);
        float wx1 = sx - x0f, wx0 = 1.f - wx1;
        float wy1 = sy - y0f, wy0 = 1.f - wy1;
        float wp = swts[t];
        int rowb = b * HWn;
        int base = t * 4;
        srow[base + 0] = rowb + y0  * WGn + x0;  swt[base + 0] = wp * wx0 * wy0;
        srow[base + 1] = rowb + y1i * WGn + x0;  swt[base + 1] = wp * wx0 * wy1;
        srow[base + 2] = rowb + y0  * WGn + x1i; swt[base + 2] = wp * wx1 * wy0;
        srow[base + 3] = rowb + y1i * WGn + x1i; swt[base + 3] = wp * wx1 * wy1;
    }
    __syncthreads();

#pragma unroll
    for (int h = 0; h < Hn; h++) {
        float acc = 0.f;
#pragma unroll
        for (int i = 0; i < 16; i++)
            acc += swt[h * 16 + i] * memory[(size_t)srow[h * 16 + i] * Dn + t];
        me[((size_t)h * BQ + bq) * Dn + t] = __float2half(acc);
    }
}

// ---------------- launch ----------------
extern "C" void kernel_launch(void* const* d_in, const int* in_sizes, int n_in,
                              void* d_out, int out_size)
{
    const float* tgt        = (const float*)d_in[0];
    const float* memory     = (const float*)d_in[1];
    const float* in_proj_w  = (const float*)d_in[2];
    const float* in_proj_b  = (const float*)d_in[3];
    const float* out_proj_w = (const float*)d_in[4];
    const float* out_proj_b = (const float*)d_in[5];
    const float* norm1_g    = (const float*)d_in[6];
    const float* norm1_b    = (const float*)d_in[7];
    const float* ref_w      = (const float*)d_in[8];
    const float* ref_b      = (const float*)d_in[9];
    const float* off_w      = (const float*)d_in[10];
    const float* off_b      = (const float*)d_in[11];
    const float* attw_w     = (const float*)d_in[12];
    const float* attw_b     = (const float*)d_in[13];
    const float* vproj_w    = (const float*)d_in[14];
    const float* vproj_b    = (const float*)d_in[15];
    const float* oproj_w    = (const float*)d_in[16];
    const float* oproj_b    = (const float*)d_in[17];
    const float* norm2_g    = (const float*)d_in[18];
    const float* norm2_b    = (const float*)d_in[19];
    const float* lin1_w     = (const float*)d_in[20];
    const float* lin1_b     = (const float*)d_in[21];
    const float* lin2_w     = (const float*)d_in[22];
    const float* lin2_b     = (const float*)d_in[23];
    const float* norm3_g    = (const float*)d_in[24];
    const float* norm3_b    = (const float*)d_in[25];
    float* out = (float*)d_out;

    float *qkv, *x1, *x2, *tmp, *wcat, *bcat, *lgb;
    __half *sah, *x2h, *cah, *meh, *ffh, *tgth;
    uint32_t *pip, *pop, *poq, *pvp, *p1w, *p2w;
    cudaGetSymbolAddress((void**)&qkv,  g_qkv);
    cudaGetSymbolAddress((void**)&sah,  g_sah);
    cudaGetSymbolAddress((void**)&x1,   g_x1);
    cudaGetSymbolAddress((void**)&x2,   g_x2);
    cudaGetSymbolAddress((void**)&x2h,  g_x2h);
    cudaGetSymbolAddress((void**)&tmp,  g_tmp);
    cudaGetSymbolAddress((void**)&cah,  g_cah);
    cudaGetSymbolAddress((void**)&meh,  g_meh);
    cudaGetSymbolAddress((void**)&ffh,  g_ffh);
    cudaGetSymbolAddress((void**)&wcat, g_wcat);
    cudaGetSymbolAddress((void**)&bcat, g_bcat);
    cudaGetSymbolAddress((void**)&lgb,  g_lg);
    cudaGetSymbolAddress((void**)&tgth, g_tgth);
    cudaGetSymbolAddress((void**)&pip,  g_pip);
    cudaGetSymbolAddress((void**)&pop,  g_pop);
    cudaGetSymbolAddress((void**)&poq,  g_poq);
    cudaGetSymbolAddress((void**)&pvp,  g_pvp);
    cudaGetSymbolAddress((void**)&p1w,  g_p1w);
    cudaGetSymbolAddress((void**)&p2w,  g_p2w);

    const int smemh = (3 * 64 * HAP + 3 * 16 * BPITCH) * 4;  // 41472
    cudaFuncSetAttribute((const void*)gemm_fp16_async, cudaFuncAttributeMaxDynamicSharedMemorySize, smemh);

    // 0. pack all weights fp16 (2816 blocks: 384+128+128+128+1024+1024);
    //    convert tgt to half; concat logits weights (fp32)
    packw_kernel<<<2816, 256>>>(in_proj_w, out_proj_w, oproj_w, vproj_w, lin1_w, lin2_w,
                                pip, pop, poq, pvp, p1w, p2w);
    tgth_kernel<<<BQ * Dn / 1024, 256>>>((const float4*)tgt, (__half2*)tgth);
    concat_w_kernel<<<128, 256>>>(ref_w, ref_b, off_w, off_b, attw_w, attw_b, wcat, bcat);
    // 1. qkv projection [4800,256]@[256,768] — fp16, fp32 out
    gemm_fp16_async<<<dim3(768 / TBN, BQ / 64), 256, smemh>>>(tgth, pip, in_proj_b, qkv, BQ, 768, Dn, 0, 0);
    // 2. fused self-attention (2 queries/thread), half out
    flash_kernel<<<Bn * Hn, 160>>>(qkv, sah);
    // 3. out_proj — fp16, fp32 out
    gemm_fp16_async<<<dim3(Dn / TBN, BQ / 64), 256, smemh>>>(sah, pop, out_proj_b, tmp, BQ, Dn, Dn, 0, 0);
    // 4. x1 = LN(tgt + sa_out)
    add_ln_kernel<<<BQ, Dn>>>(tgt, tmp, norm1_g, norm1_b, x1, nullptr);
    // 5. logits — fp32 (accuracy-critical)
    gemm_f32_kernel<<<dim3(128 / BNf, BQ / BM), 256>>>(x1, wcat, bcat, lgb, BQ, 128, Dn);
    // 6. sampler2: gather raw memory -> half m_eff
    sampler2_kernel<<<BQ, 256>>>(lgb, memory, meh);
    // 7. per-head projection — fp16, half out
    gemm_proj_h<<<dim3(Hn, BQ / 64), 128>>>(meh, pvp, vproj_b, cah);
    // 8. oproj — fp16, fp32 out
    gemm_fp16_async<<<dim3(Dn / TBN, BQ / 64), 256, smemh>>>(cah, poq, oproj_b, tmp, BQ, Dn, Dn, 0, 0);
    // 9. x2 = LN(x1 + ca_out); x2h = half(x2)
    add_ln_kernel<<<BQ, Dn>>>(x1, tmp, norm2_g, norm2_b, x2, x2h);
    // 10. FFN lin1 + ReLU — fp16, half out
    gemm_fp16_async<<<dim3(Fn / TBN, BQ / 64), 256, smemh>>>(x2h, p1w, lin1_b, ffh, BQ, Fn, Dn, 1, 1);
    // 11. FFN lin2 — fp16, fp32 out
    gemm_fp16_async<<<dim3(Dn / TBN, BQ / 64), 256, smemh>>>(ffh, p2w, lin2_b, tmp, BQ, Dn, Fn, 0, 0);
    // 12. out = LN(x2 + ffn)
    add_ln_kernel<<<BQ, Dn>>>(x2, tmp, norm3_g, norm3_b, out, nullptr);
}